// round 11
// baseline (speedup 1.0000x reference)
#include <cuda_runtime.h>
#include <cuda_bf16.h>
#include <cstdint>

#define B_SZ    2
#define S_LEN   2048
#define D_MODEL 1024
#define NHEAD   16
#define HD      64
#define M_ROWS  (B_SZ * S_LEN)      // 4096
#define QKV_LD  (3 * D_MODEL)       // 3072
#define DSQ     (D_MODEL * D_MODEL) // 1048576

// bf16 hi/lo scratch (device globals)
__device__ __nv_bfloat16 g_xh [(size_t)M_ROWS * D_MODEL];
__device__ __nv_bfloat16 g_xl [(size_t)M_ROWS * D_MODEL];
__device__ __nv_bfloat16 g_wh [(size_t)3 * DSQ];               // wq|wk|wv
__device__ __nv_bfloat16 g_wl [(size_t)3 * DSQ];
__device__ __nv_bfloat16 g_woh[(size_t)DSQ];
__device__ __nv_bfloat16 g_wol[(size_t)DSQ];
__device__ __nv_bfloat16 g_qkvh[(size_t)M_ROWS * QKV_LD];      // Q(x0.125)|K|V
__device__ __nv_bfloat16 g_qkvl[(size_t)M_ROWS * QKV_LD];
__device__ __nv_bfloat16 g_atth[(size_t)M_ROWS * D_MODEL];
__device__ __nv_bfloat16 g_attl[(size_t)M_ROWS * D_MODEL];

__device__ __forceinline__ uint32_t smem_u32(const void* p) {
    uint32_t a;
    asm("{ .reg .u64 t; cvta.to.shared.u64 t, %1; cvt.u32.u64 %0, t; }"
        : "=r"(a) : "l"(p));
    return a;
}

#define LDM4(r, addr) \
    asm volatile("ldmatrix.sync.aligned.m8n8.x4.shared.b16 {%0,%1,%2,%3}, [%4];" \
        : "=r"((r)[0]), "=r"((r)[1]), "=r"((r)[2]), "=r"((r)[3]) : "r"(addr))

#define LDM4T(r, addr) \
    asm volatile("ldmatrix.sync.aligned.m8n8.x4.trans.shared.b16 {%0,%1,%2,%3}, [%4];" \
        : "=r"((r)[0]), "=r"((r)[1]), "=r"((r)[2]), "=r"((r)[3]) : "r"(addr))

#define MMA_BF16(d, a, b0, b1) \
    asm volatile("mma.sync.aligned.m16n8k16.row.col.f32.bf16.bf16.f32 " \
        "{%0,%1,%2,%3}, {%4,%5,%6,%7}, {%8,%9}, {%0,%1,%2,%3};" \
        : "+f"((d)[0]), "+f"((d)[1]), "+f"((d)[2]), "+f"((d)[3]) \
        : "r"((a)[0]), "r"((a)[1]), "r"((a)[2]), "r"((a)[3]), "r"(b0), "r"(b1))

#define CP16(dst, src) \
    asm volatile("cp.async.cg.shared.global [%0], [%1], 16;" \
        :: "r"(dst), "l"(src) : "memory")
#define CP_COMMIT() asm volatile("cp.async.commit_group;" ::: "memory")
#define CP_WAIT1()  asm volatile("cp.async.wait_group 1;" ::: "memory")
#define CP_WAIT2()  asm volatile("cp.async.wait_group 2;" ::: "memory")

__device__ __forceinline__ uint32_t pack2(__nv_bfloat16 a, __nv_bfloat16 b) {
    return (uint32_t)__bfloat16_as_ushort(a) |
           ((uint32_t)__bfloat16_as_ushort(b) << 16);
}

__device__ __forceinline__ void cvt4(float4 v, uint2& h, uint2& l) {
    __nv_bfloat16 h0 = __float2bfloat16_rn(v.x);
    __nv_bfloat16 h1 = __float2bfloat16_rn(v.y);
    __nv_bfloat16 h2 = __float2bfloat16_rn(v.z);
    __nv_bfloat16 h3 = __float2bfloat16_rn(v.w);
    __nv_bfloat16 l0 = __float2bfloat16_rn(v.x - __bfloat162float(h0));
    __nv_bfloat16 l1 = __float2bfloat16_rn(v.y - __bfloat162float(h1));
    __nv_bfloat16 l2 = __float2bfloat16_rn(v.z - __bfloat162float(h2));
    __nv_bfloat16 l3 = __float2bfloat16_rn(v.w - __bfloat162float(h3));
    h.x = pack2(h0, h1); h.y = pack2(h2, h3);
    l.x = pack2(l0, l1); l.y = pack2(l2, l3);
}

__device__ __forceinline__ uint32_t hi_lo_pack(float a, float b, uint32_t& lo) {
    __nv_bfloat16 ha = __float2bfloat16_rn(a);
    __nv_bfloat16 hb = __float2bfloat16_rn(b);
    lo = pack2(__float2bfloat16_rn(a - __bfloat162float(ha)),
               __float2bfloat16_rn(b - __bfloat162float(hb)));
    return pack2(ha, hb);
}

// ---------------------------------------------------------------------------
// Fused one-shot f32 -> bf16 hi/lo conversion of all five tensors
// ---------------------------------------------------------------------------
#define XF4 (M_ROWS * D_MODEL / 4)   // 1048576
#define WF4 (DSQ / 4)                // 262144

__global__ void cvt_all(
    const float* __restrict__ x,  const float* __restrict__ wq,
    const float* __restrict__ wk, const float* __restrict__ wv,
    const float* __restrict__ wo,
    __nv_bfloat16* __restrict__ xh,  __nv_bfloat16* __restrict__ xl,
    __nv_bfloat16* __restrict__ wh,  __nv_bfloat16* __restrict__ wl,
    __nv_bfloat16* __restrict__ woh, __nv_bfloat16* __restrict__ wol)
{
    const int i = blockIdx.x * blockDim.x + threadIdx.x;
    const float* src; __nv_bfloat16 *oh, *ol; int j;
    if (i < XF4)              { src = x;  oh = xh;  ol = xl;  j = i; }
    else if (i < XF4 + WF4)   { src = wq; oh = wh;  ol = wl;  j = i - XF4; }
    else if (i < XF4 + 2*WF4) { src = wk; oh = wh + DSQ;  ol = wl + DSQ;  j = i - XF4 - WF4; }
    else if (i < XF4 + 3*WF4) { src = wv; oh = wh + 2*DSQ; ol = wl + 2*DSQ; j = i - XF4 - 2*WF4; }
    else if (i < XF4 + 4*WF4) { src = wo; oh = woh; ol = wol; j = i - XF4 - 3*WF4; }
    else return;
    float4 v = reinterpret_cast<const float4*>(src)[j];
    uint2 hh, ll;
    cvt4(v, hh, ll);
    reinterpret_cast<uint2*>(oh)[j] = hh;
    reinterpret_cast<uint2*>(ol)[j] = ll;
}

// ===========================================================================
// mma.sync bf16x3 GEMM, pre-split inputs, 4-stage cp.async (BK=16).
// Term-outer MMA schedule: accumulator reuse distance 16 (no RAW chains).
// CTA 128x128, 8 warps, warp tile 64x32, 2 CTAs/SM.
// ===========================================================================
#define ROWB    48
#define T_AH    0
#define T_AL    6144
#define T_BH    12288
#define T_BL    18432
#define STAGE_B 24576
#define GEMM_SMEM_BYTES (4 * STAGE_B)  // 98304

template <bool HAS_BIAS, bool OUT_BF16, bool SCALE_Q8>
__global__ void __launch_bounds__(256, 2) mma_gemm(
    const __nv_bfloat16* __restrict__ Ah, const __nv_bfloat16* __restrict__ Al,
    const __nv_bfloat16* __restrict__ Wh, const __nv_bfloat16* __restrict__ Wl,
    const float* __restrict__ bias,
    float* __restrict__ C,
    __nv_bfloat16* __restrict__ Ch, __nv_bfloat16* __restrict__ Cl,
    int K, int ldc)
{
    extern __shared__ __align__(128) char smem[];
    const uint32_t sbase = smem_u32(smem);
    const int tid  = threadIdx.x;
    const int lane = tid & 31;
    const int bx   = blockIdx.x;
    const int bm   = blockIdx.y * 128;
    const int bn   = (bx & 7) * 128;
    const int cn   = (bx >> 3) * D_MODEL + bn;
    const size_t woff = (size_t)(bx >> 3) * DSQ;

    const int wm = (tid >> 7) * 64;
    const int wn = ((tid >> 5) & 3) * 32;

    const uint32_t a_off = (uint32_t)(wm + (lane & 15)) * ROWB + (lane >> 4) * 16;
    const uint32_t b_off = (uint32_t)(wn + (lane >> 4) * 8 + (lane & 7)) * ROWB
                           + ((lane >> 3) & 1) * 16;

    const int lr = tid >> 1;
    const int lg = (tid & 1) * 8;
    const __nv_bfloat16* pAh = Ah + (size_t)(bm + lr) * K + lg;
    const __nv_bfloat16* pAl = Al + (size_t)(bm + lr) * K + lg;
    const __nv_bfloat16* pWh = Wh + woff + (size_t)(bn + lr) * K + lg;
    const __nv_bfloat16* pWl = Wl + woff + (size_t)(bn + lr) * K + lg;
    const uint32_t soff = (uint32_t)lr * ROWB + (tid & 1) * 16;

    float acc[4][4][4];
#pragma unroll
    for (int i = 0; i < 4; i++)
#pragma unroll
        for (int j = 0; j < 4; j++)
#pragma unroll
            for (int r = 0; r < 4; r++) acc[i][j][r] = 0.f;

    const int nch = K / 16;

#pragma unroll
    for (int c = 0; c < 3; c++) {
        const uint32_t sb = sbase + c * STAGE_B;
        const int k0 = c * 16;
        CP16(sb + T_AH + soff, pAh + k0);
        CP16(sb + T_AL + soff, pAl + k0);
        CP16(sb + T_BH + soff, pWh + k0);
        CP16(sb + T_BL + soff, pWl + k0);
        CP_COMMIT();
    }

    for (int c = 0; c < nch; c++) {
        CP_WAIT2();
        __syncthreads();

        if (c + 3 < nch) {
            const uint32_t sb = sbase + ((c + 3) & 3) * STAGE_B;
            const int k0 = (c + 3) * 16;
            CP16(sb + T_AH + soff, pAh + k0);
            CP16(sb + T_AL + soff, pAl + k0);
            CP16(sb + T_BH + soff, pWh + k0);
            CP16(sb + T_BL + soff, pWl + k0);
        }
        CP_COMMIT();

        const uint32_t stb = sbase + (c & 3) * STAGE_B;
        uint32_t ah[4][4], al[4][4];
#pragma unroll
        for (int mf = 0; mf < 4; mf++) {
            LDM4(ah[mf], stb + T_AH + a_off + mf * (16 * ROWB));
            LDM4(al[mf], stb + T_AL + a_off + mf * (16 * ROWB));
        }
        uint32_t bh[2][4], bl[2][4];
#pragma unroll
        for (int p = 0; p < 2; p++) {
            LDM4(bh[p], stb + T_BH + b_off + p * (16 * ROWB));
            LDM4(bl[p], stb + T_BL + b_off + p * (16 * ROWB));
        }

        // Term-outer schedule: 16 independent MMAs between acc reuses.
#pragma unroll
        for (int term = 0; term < 3; term++) {
#pragma unroll
            for (int mf = 0; mf < 4; mf++) {
#pragma unroll
                for (int nf = 0; nf < 4; nf++) {
                    const uint32_t* aa = (term == 2) ? al[mf] : ah[mf];
                    const uint32_t* bb = (term == 1) ? bl[nf >> 1] : bh[nf >> 1];
                    MMA_BF16(acc[mf][nf], aa,
                             bb[(nf & 1) * 2], bb[(nf & 1) * 2 + 1]);
                }
            }
        }
    }

    const int g  = lane >> 2;
    const int t2 = (lane & 3) * 2;
    const float sc = (SCALE_Q8 && bx < 8) ? 0.125f : 1.0f;
#pragma unroll
    for (int mf = 0; mf < 4; mf++) {
#pragma unroll
        for (int nf = 0; nf < 4; nf++) {
            const int m = bm + wm + mf * 16 + g;
            const int n = cn + wn + nf * 8 + t2;
            float2 v0, v1;
            v0.x = acc[mf][nf][0]; v0.y = acc[mf][nf][1];
            v1.x = acc[mf][nf][2]; v1.y = acc[mf][nf][3];
            if (OUT_BF16) {
                v0.x *= sc; v0.y *= sc; v1.x *= sc; v1.y *= sc;
                uint32_t l0_, l1_;
                uint32_t h0_ = hi_lo_pack(v0.x, v0.y, l0_);
                uint32_t h1_ = hi_lo_pack(v1.x, v1.y, l1_);
                *reinterpret_cast<uint32_t*>(&Ch[(size_t)m * ldc + n]) = h0_;
                *reinterpret_cast<uint32_t*>(&Cl[(size_t)m * ldc + n]) = l0_;
                *reinterpret_cast<uint32_t*>(&Ch[(size_t)(m + 8) * ldc + n]) = h1_;
                *reinterpret_cast<uint32_t*>(&Cl[(size_t)(m + 8) * ldc + n]) = l1_;
            } else {
                if (HAS_BIAS) {
                    const float2 bv = *reinterpret_cast<const float2*>(&bias[n]);
                    v0.x += bv.x; v0.y += bv.y;
                    v1.x += bv.x; v1.y += bv.y;
                }
                *reinterpret_cast<float2*>(&C[(size_t)m * ldc + n]) = v0;
                *reinterpret_cast<float2*>(&C[(size_t)(m + 8) * ldc + n]) = v1;
            }
        }
    }
}

// ===========================================================================
// Tensor-core causal flash attention, 3-stage cp.async KV ring.
// Interleaved accumulator pairs (reuse distance 2 between MMAs).
// ===========================================================================
#define FROWB 144
#define KV_KH 0
#define KV_KL 9216
#define KV_VH 18432
#define KV_VL 27648
#define KV_STAGE 36864
#define SQH   0
#define SQL   18432
#define FLASH_SMEM_BYTES (3 * KV_STAGE)   // 110592

__global__ void __launch_bounds__(256) flash_mma(
    const __nv_bfloat16* __restrict__ qkvh,
    const __nv_bfloat16* __restrict__ qkvl,
    __nv_bfloat16* __restrict__ atth,
    __nv_bfloat16* __restrict__ attl)
{
    extern __shared__ __align__(128) char smem[];
    const uint32_t sbase = smem_u32(smem);
    const int tid  = threadIdx.x;
    const int lane = tid & 31;
    const int w    = tid >> 5;
    const int qt   = (gridDim.x - 1) - blockIdx.x;
    const int h    = blockIdx.y;
    const int b    = blockIdx.z;

    const size_t head_base = (size_t)b * S_LEN * QKV_LD + (size_t)h * HD;

    {
        const int r = tid >> 1;
        const int g0 = (tid & 1) * 4;
        const __nv_bfloat16* qrh = qkvh + head_base + (size_t)(qt * 128 + r) * QKV_LD;
        const __nv_bfloat16* qrl = qkvl + head_base + (size_t)(qt * 128 + r) * QKV_LD;
#pragma unroll
        for (int t = 0; t < 4; t++) {
            const int gg = g0 + t;
            const uint32_t off = (uint32_t)r * FROWB + gg * 16;
            *reinterpret_cast<uint4*>(smem + SQH + off) =
                *reinterpret_cast<const uint4*>(qrh + gg * 8);
            *reinterpret_cast<uint4*>(smem + SQL + off) =
                *reinterpret_cast<const uint4*>(qrl + gg * 8);
        }
    }
    __syncthreads();

    uint32_t qh[4][4], ql[4][4];
    {
        const uint32_t a_off = (uint32_t)(w * 16 + (lane & 15)) * FROWB
                               + ((lane >> 4) * 8) * 2;
#pragma unroll
        for (int ks = 0; ks < 4; ks++) {
            LDM4(qh[ks], sbase + SQH + a_off + ks * 32);
            LDM4(ql[ks], sbase + SQL + a_off + ks * 32);
        }
    }
    __syncthreads();

    float o[8][4];
#pragma unroll
    for (int nf = 0; nf < 8; nf++)
#pragma unroll
        for (int r = 0; r < 4; r++) o[nf][r] = 0.f;
    float m0 = -1e30f, m1 = -1e30f, l0 = 0.f, l1 = 0.f;

    const int g  = lane >> 2;
    const int t2 = (lane & 3) * 2;
    const int wrow = qt * 128 + w * 16;
    const int row0 = wrow + g;
    const int row1 = row0 + 8;

    const uint32_t kb_off = (uint32_t)((lane >> 4) * 8 + (lane & 7)) * FROWB
                            + (((lane >> 3) & 1) * 8) * 2;
    const uint32_t vt_row = (uint32_t)(lane & 15) * FROWB + ((lane >> 4) * 8) * 2;

    const int klr = tid >> 2;
    const int kg0 = (tid & 3) * 2;

    const int kt_end = 2 * qt + 1;

#pragma unroll
    for (int c = 0; c < 2; c++) {
        const uint32_t sb = sbase + c * KV_STAGE;
        const size_t rowb = head_base + (size_t)(c * 64 + klr) * QKV_LD;
#pragma unroll
        for (int t = 0; t < 2; t++) {
            const int gg = kg0 + t;
            const uint32_t off = (uint32_t)klr * FROWB + gg * 16;
            CP16(sb + KV_KH + off, qkvh + rowb + D_MODEL + gg * 8);
            CP16(sb + KV_KL + off, qkvl + rowb + D_MODEL + gg * 8);
            CP16(sb + KV_VH + off, qkvh + rowb + 2 * D_MODEL + gg * 8);
            CP16(sb + KV_VL + off, qkvl + rowb + 2 * D_MODEL + gg * 8);
        }
        CP_COMMIT();
    }

    for (int kt = 0; kt <= kt_end; kt++) {
        CP_WAIT1();
        __syncthreads();

        if (kt + 2 <= kt_end) {
            const uint32_t sb = sbase + ((kt + 2) % 3) * KV_STAGE;
            const size_t rowb = head_base + (size_t)((kt + 2) * 64 + klr) * QKV_LD;
#pragma unroll
            for (int t = 0; t < 2; t++) {
                const int gg = kg0 + t;
                const uint32_t off = (uint32_t)klr * FROWB + gg * 16;
                CP16(sb + KV_KH + off, qkvh + rowb + D_MODEL + gg * 8);
                CP16(sb + KV_KL + off, qkvl + rowb + D_MODEL + gg * 8);
                CP16(sb + KV_VH + off, qkvh + rowb + 2 * D_MODEL + gg * 8);
                CP16(sb + KV_VL + off, qkvl + rowb + 2 * D_MODEL + gg * 8);
            }
        }
        CP_COMMIT();

        const bool active = (kt * 64 <= wrow + 15);
        if (active) {
            const uint32_t stb = sbase + (kt % 3) * KV_STAGE;
            float s[8][4];
#pragma unroll
            for (int nf = 0; nf < 8; nf++)
#pragma unroll
                for (int r = 0; r < 4; r++) s[nf][r] = 0.f;

#pragma unroll
            for (int ks = 0; ks < 4; ks++) {
#pragma unroll
                for (int p = 0; p < 4; p++) {
                    uint32_t kh[4], kl[4];
                    LDM4(kh, stb + KV_KH + kb_off + p * (16 * FROWB) + ks * 32);
                    LDM4(kl, stb + KV_KL + kb_off + p * (16 * FROWB) + ks * 32);
                    // Interleaved pairs: reuse distance 2
                    MMA_BF16(s[2 * p],     qh[ks], kh[0], kh[1]);
                    MMA_BF16(s[2 * p + 1], qh[ks], kh[2], kh[3]);
                    MMA_BF16(s[2 * p],     qh[ks], kl[0], kl[1]);
                    MMA_BF16(s[2 * p + 1], qh[ks], kl[2], kl[3]);
                    MMA_BF16(s[2 * p],     ql[ks], kh[0], kh[1]);
                    MMA_BF16(s[2 * p + 1], ql[ks], kh[2], kh[3]);
                }
            }

            if (kt * 64 + 63 > wrow) {
#pragma unroll
                for (int nf = 0; nf < 8; nf++) {
                    const int c0 = kt * 64 + nf * 8 + t2;
                    if (c0     > row0) s[nf][0] = -1e30f;
                    if (c0 + 1 > row0) s[nf][1] = -1e30f;
                    if (c0     > row1) s[nf][2] = -1e30f;
                    if (c0 + 1 > row1) s[nf][3] = -1e30f;
                }
            }

            float mx0 = s[0][0], mx1 = s[0][2];
#pragma unroll
            for (int nf = 0; nf < 8; nf++) {
                mx0 = fmaxf(mx0, fmaxf(s[nf][0], s[nf][1]));
                mx1 = fmaxf(mx1, fmaxf(s[nf][2], s[nf][3]));
            }
            mx0 = fmaxf(mx0, __shfl_xor_sync(0xffffffffu, mx0, 1));
            mx0 = fmaxf(mx0, __shfl_xor_sync(0xffffffffu, mx0, 2));
            mx1 = fmaxf(mx1, __shfl_xor_sync(0xffffffffu, mx1, 1));
            mx1 = fmaxf(mx1, __shfl_xor_sync(0xffffffffu, mx1, 2));

            const float nm0 = fmaxf(m0, mx0), nm1 = fmaxf(m1, mx1);
            const float a0 = __expf(m0 - nm0), a1 = __expf(m1 - nm1);
            m0 = nm0; m1 = nm1;

            float sum0 = 0.f, sum1 = 0.f;
#pragma unroll
            for (int nf = 0; nf < 8; nf++) {
                s[nf][0] = __expf(s[nf][0] - nm0);
                s[nf][1] = __expf(s[nf][1] - nm0);
                s[nf][2] = __expf(s[nf][2] - nm1);
                s[nf][3] = __expf(s[nf][3] - nm1);
                sum0 += s[nf][0] + s[nf][1];
                sum1 += s[nf][2] + s[nf][3];
            }
            sum0 += __shfl_xor_sync(0xffffffffu, sum0, 1);
            sum0 += __shfl_xor_sync(0xffffffffu, sum0, 2);
            sum1 += __shfl_xor_sync(0xffffffffu, sum1, 1);
            sum1 += __shfl_xor_sync(0xffffffffu, sum1, 2);
            l0 = l0 * a0 + sum0;
            l1 = l1 * a1 + sum1;

#pragma unroll
            for (int nf = 0; nf < 8; nf++) {
                o[nf][0] *= a0; o[nf][1] *= a0;
                o[nf][2] *= a1; o[nf][3] *= a1;
            }

#pragma unroll
            for (int j = 0; j < 4; j++) {
                uint32_t ph[4], pl[4];
                ph[0] = hi_lo_pack(s[2 * j][0],     s[2 * j][1],     pl[0]);
                ph[1] = hi_lo_pack(s[2 * j][2],     s[2 * j][3],     pl[1]);
                ph[2] = hi_lo_pack(s[2 * j + 1][0], s[2 * j + 1][1], pl[2]);
                ph[3] = hi_lo_pack(s[2 * j + 1][2], s[2 * j + 1][3], pl[3]);

                const uint32_t vbase = (uint32_t)(j * 16) * FROWB + vt_row;
#pragma unroll
                for (int hg = 0; hg < 4; hg++) {
                    uint32_t vh[4], vl[4];
                    LDM4T(vh, stb + KV_VH + vbase + hg * 32);
                    LDM4T(vl, stb + KV_VL + vbase + hg * 32);
                    // Interleaved pairs: reuse distance 2
                    MMA_BF16(o[2 * hg],     ph, vh[0], vh[1]);
                    MMA_BF16(o[2 * hg + 1], ph, vh[2], vh[3]);
                    MMA_BF16(o[2 * hg],     ph, vl[0], vl[1]);
                    MMA_BF16(o[2 * hg + 1], ph, vl[2], vl[3]);
                    MMA_BF16(o[2 * hg],     pl, vh[0], vh[1]);
                    MMA_BF16(o[2 * hg + 1], pl, vh[2], vh[3]);
                }
            }
        }
    }

    const float inv0 = 1.f / l0, inv1 = 1.f / l1;
    const size_t ob = ((size_t)b * S_LEN + qt * 128 + w * 16) * D_MODEL
                      + (size_t)h * HD;
#pragma unroll
    for (int nf = 0; nf < 8; nf++) {
        const int c = nf * 8 + t2;
        uint32_t lo0, lo1;
        uint32_t hi0 = hi_lo_pack(o[nf][0] * inv0, o[nf][1] * inv0, lo0);
        uint32_t hi1 = hi_lo_pack(o[nf][2] * inv1, o[nf][3] * inv1, lo1);
        *reinterpret_cast<uint32_t*>(&atth[ob + (size_t)g * D_MODEL + c]) = hi0;
        *reinterpret_cast<uint32_t*>(&attl[ob + (size_t)g * D_MODEL + c]) = lo0;
        *reinterpret_cast<uint32_t*>(&atth[ob + (size_t)(g + 8) * D_MODEL + c]) = hi1;
        *reinterpret_cast<uint32_t*>(&attl[ob + (size_t)(g + 8) * D_MODEL + c]) = lo1;
    }
}

// ---------------------------------------------------------------------------
extern "C" void kernel_launch(void* const* d_in, const int* in_sizes, int n_in,
                              void* d_out, int out_size)
{
    const float* x    = (const float*)d_in[0];
    const float* wq   = (const float*)d_in[1];
    const float* wk   = (const float*)d_in[2];
    const float* wv   = (const float*)d_in[3];
    const float* wo_w = (const float*)d_in[4];
    const float* wo_b = (const float*)d_in[5];
    float* out = (float*)d_out;

    __nv_bfloat16 *xh, *xl, *wh, *wl, *woh, *wol, *qkvh, *qkvl, *atth, *attl;
    cudaGetSymbolAddress((void**)&xh,   g_xh);
    cudaGetSymbolAddress((void**)&xl,   g_xl);
    cudaGetSymbolAddress((void**)&wh,   g_wh);
    cudaGetSymbolAddress((void**)&wl,   g_wl);
    cudaGetSymbolAddress((void**)&woh,  g_woh);
    cudaGetSymbolAddress((void**)&wol,  g_wol);
    cudaGetSymbolAddress((void**)&qkvh, g_qkvh);
    cudaGetSymbolAddress((void**)&qkvl, g_qkvl);
    cudaGetSymbolAddress((void**)&atth, g_atth);
    cudaGetSymbolAddress((void**)&attl, g_attl);

    static bool attr_done = false;
    if (!attr_done) {
        cudaFuncSetAttribute((const void*)mma_gemm<false, true, true>,
                             cudaFuncAttributeMaxDynamicSharedMemorySize,
                             GEMM_SMEM_BYTES);
        cudaFuncSetAttribute((const void*)mma_gemm<true, false, false>,
                             cudaFuncAttributeMaxDynamicSharedMemorySize,
                             GEMM_SMEM_BYTES);
        cudaFuncSetAttribute((const void*)flash_mma,
                             cudaFuncAttributeMaxDynamicSharedMemorySize,
                             FLASH_SMEM_BYTES);
        attr_done = true;
    }

    const int total4 = XF4 + 4 * WF4;
    cvt_all<<<(total4 + 255) / 256, 256>>>(x, wq, wk, wv, wo_w,
                                           xh, xl, wh, wl, woh, wol);

    const dim3 qkv_grid(24, M_ROWS / 128);
    mma_gemm<false, true, true><<<qkv_grid, 256, GEMM_SMEM_BYTES>>>(
        xh, xl, wh, wl, nullptr, nullptr, qkvh, qkvl, D_MODEL, QKV_LD);

    const dim3 flash_grid(S_LEN / 128, NHEAD, B_SZ);
    flash_mma<<<flash_grid, 256, FLASH_SMEM_BYTES>>>(qkvh, qkvl, atth, attl);

    const dim3 o_grid(8, M_ROWS / 128);
    mma_gemm<true, false, false><<<o_grid, 256, GEMM_SMEM_BYTES>>>(
        atth, attl, woh, wol, wo_b, out, nullptr, nullptr, D_MODEL, D_MODEL);
}

// round 12
// speedup vs baseline: 1.0714x; 1.0714x over previous
#include <cuda_runtime.h>
#include <cuda_bf16.h>
#include <cstdint>

#define B_SZ    2
#define S_LEN   2048
#define D_MODEL 1024
#define NHEAD   16
#define HD      64
#define M_ROWS  (B_SZ * S_LEN)      // 4096
#define QKV_LD  (3 * D_MODEL)       // 3072
#define DSQ     (D_MODEL * D_MODEL) // 1048576

// bf16 hi/lo scratch (device globals)
__device__ __nv_bfloat16 g_xh [(size_t)M_ROWS * D_MODEL];
__device__ __nv_bfloat16 g_xl [(size_t)M_ROWS * D_MODEL];
__device__ __nv_bfloat16 g_wh [(size_t)3 * DSQ];               // wq|wk|wv
__device__ __nv_bfloat16 g_wl [(size_t)3 * DSQ];
__device__ __nv_bfloat16 g_woh[(size_t)DSQ];
__device__ __nv_bfloat16 g_wol[(size_t)DSQ];
__device__ __nv_bfloat16 g_qkvh[(size_t)M_ROWS * QKV_LD];      // Q(x0.125)|K|V
__device__ __nv_bfloat16 g_qkvl[(size_t)M_ROWS * QKV_LD];
__device__ __nv_bfloat16 g_atth[(size_t)M_ROWS * D_MODEL];
__device__ __nv_bfloat16 g_attl[(size_t)M_ROWS * D_MODEL];

__device__ __forceinline__ uint32_t smem_u32(const void* p) {
    uint32_t a;
    asm("{ .reg .u64 t; cvta.to.shared.u64 t, %1; cvt.u32.u64 %0, t; }"
        : "=r"(a) : "l"(p));
    return a;
}

#define LDM4(r, addr) \
    asm volatile("ldmatrix.sync.aligned.m8n8.x4.shared.b16 {%0,%1,%2,%3}, [%4];" \
        : "=r"((r)[0]), "=r"((r)[1]), "=r"((r)[2]), "=r"((r)[3]) : "r"(addr))

#define LDM4T(r, addr) \
    asm volatile("ldmatrix.sync.aligned.m8n8.x4.trans.shared.b16 {%0,%1,%2,%3}, [%4];" \
        : "=r"((r)[0]), "=r"((r)[1]), "=r"((r)[2]), "=r"((r)[3]) : "r"(addr))

#define MMA_BF16(d, a, b0, b1) \
    asm volatile("mma.sync.aligned.m16n8k16.row.col.f32.bf16.bf16.f32 " \
        "{%0,%1,%2,%3}, {%4,%5,%6,%7}, {%8,%9}, {%0,%1,%2,%3};" \
        : "+f"((d)[0]), "+f"((d)[1]), "+f"((d)[2]), "+f"((d)[3]) \
        : "r"((a)[0]), "r"((a)[1]), "r"((a)[2]), "r"((a)[3]), "r"(b0), "r"(b1))

#define CP16(dst, src) \
    asm volatile("cp.async.cg.shared.global [%0], [%1], 16;" \
        :: "r"(dst), "l"(src) : "memory")
#define CP_COMMIT() asm volatile("cp.async.commit_group;" ::: "memory")
#define CP_WAIT2()  asm volatile("cp.async.wait_group 2;" ::: "memory")

__device__ __forceinline__ uint32_t pack2(__nv_bfloat16 a, __nv_bfloat16 b) {
    return (uint32_t)__bfloat16_as_ushort(a) |
           ((uint32_t)__bfloat16_as_ushort(b) << 16);
}

__device__ __forceinline__ void cvt4(float4 v, uint2& h, uint2& l) {
    __nv_bfloat16 h0 = __float2bfloat16_rn(v.x);
    __nv_bfloat16 h1 = __float2bfloat16_rn(v.y);
    __nv_bfloat16 h2 = __float2bfloat16_rn(v.z);
    __nv_bfloat16 h3 = __float2bfloat16_rn(v.w);
    __nv_bfloat16 l0 = __float2bfloat16_rn(v.x - __bfloat162float(h0));
    __nv_bfloat16 l1 = __float2bfloat16_rn(v.y - __bfloat162float(h1));
    __nv_bfloat16 l2 = __float2bfloat16_rn(v.z - __bfloat162float(h2));
    __nv_bfloat16 l3 = __float2bfloat16_rn(v.w - __bfloat162float(h3));
    h.x = pack2(h0, h1); h.y = pack2(h2, h3);
    l.x = pack2(l0, l1); l.y = pack2(l2, l3);
}

__device__ __forceinline__ uint32_t hi_lo_pack(float a, float b, uint32_t& lo) {
    __nv_bfloat16 ha = __float2bfloat16_rn(a);
    __nv_bfloat16 hb = __float2bfloat16_rn(b);
    lo = pack2(__float2bfloat16_rn(a - __bfloat162float(ha)),
               __float2bfloat16_rn(b - __bfloat162float(hb)));
    return pack2(ha, hb);
}

// ---------------------------------------------------------------------------
// Fused one-shot f32 -> bf16 hi/lo conversion of all five tensors
// ---------------------------------------------------------------------------
#define XF4 (M_ROWS * D_MODEL / 4)   // 1048576
#define WF4 (DSQ / 4)                // 262144

__global__ void cvt_all(
    const float* __restrict__ x,  const float* __restrict__ wq,
    const float* __restrict__ wk, const float* __restrict__ wv,
    const float* __restrict__ wo,
    __nv_bfloat16* __restrict__ xh,  __nv_bfloat16* __restrict__ xl,
    __nv_bfloat16* __restrict__ wh,  __nv_bfloat16* __restrict__ wl,
    __nv_bfloat16* __restrict__ woh, __nv_bfloat16* __restrict__ wol)
{
    const int i = blockIdx.x * blockDim.x + threadIdx.x;
    const float* src; __nv_bfloat16 *oh, *ol; int j;
    if (i < XF4)              { src = x;  oh = xh;  ol = xl;  j = i; }
    else if (i < XF4 + WF4)   { src = wq; oh = wh;  ol = wl;  j = i - XF4; }
    else if (i < XF4 + 2*WF4) { src = wk; oh = wh + DSQ;  ol = wl + DSQ;  j = i - XF4 - WF4; }
    else if (i < XF4 + 3*WF4) { src = wv; oh = wh + 2*DSQ; ol = wl + 2*DSQ; j = i - XF4 - 2*WF4; }
    else if (i < XF4 + 4*WF4) { src = wo; oh = woh; ol = wol; j = i - XF4 - 3*WF4; }
    else return;
    float4 v = reinterpret_cast<const float4*>(src)[j];
    uint2 hh, ll;
    cvt4(v, hh, ll);
    reinterpret_cast<uint2*>(oh)[j] = hh;
    reinterpret_cast<uint2*>(ol)[j] = ll;
}

// ===========================================================================
// mma.sync bf16x3 GEMM, pre-split inputs, 4-stage cp.async (BK=16).
// R10 schedule (hh/hl/lh per acc) — verified fastest.
// CTA 128x128, 8 warps, warp tile 64x32, 2 CTAs/SM.
// ===========================================================================
#define ROWB    48
#define T_AH    0
#define T_AL    6144
#define T_BH    12288
#define T_BL    18432
#define STAGE_B 24576
#define GEMM_SMEM_BYTES (4 * STAGE_B)  // 98304

template <bool HAS_BIAS, bool OUT_BF16, bool SCALE_Q8>
__global__ void __launch_bounds__(256, 2) mma_gemm(
    const __nv_bfloat16* __restrict__ Ah, const __nv_bfloat16* __restrict__ Al,
    const __nv_bfloat16* __restrict__ Wh, const __nv_bfloat16* __restrict__ Wl,
    const float* __restrict__ bias,
    float* __restrict__ C,
    __nv_bfloat16* __restrict__ Ch, __nv_bfloat16* __restrict__ Cl,
    int K, int ldc)
{
    extern __shared__ __align__(128) char smem[];
    const uint32_t sbase = smem_u32(smem);
    const int tid  = threadIdx.x;
    const int lane = tid & 31;
    const int bx   = blockIdx.x;
    const int bm   = blockIdx.y * 128;
    const int bn   = (bx & 7) * 128;
    const int cn   = (bx >> 3) * D_MODEL + bn;
    const size_t woff = (size_t)(bx >> 3) * DSQ;

    const int wm = (tid >> 7) * 64;
    const int wn = ((tid >> 5) & 3) * 32;

    const uint32_t a_off = (uint32_t)(wm + (lane & 15)) * ROWB + (lane >> 4) * 16;
    const uint32_t b_off = (uint32_t)(wn + (lane >> 4) * 8 + (lane & 7)) * ROWB
                           + ((lane >> 3) & 1) * 16;

    const int lr = tid >> 1;
    const int lg = (tid & 1) * 8;
    const __nv_bfloat16* pAh = Ah + (size_t)(bm + lr) * K + lg;
    const __nv_bfloat16* pAl = Al + (size_t)(bm + lr) * K + lg;
    const __nv_bfloat16* pWh = Wh + woff + (size_t)(bn + lr) * K + lg;
    const __nv_bfloat16* pWl = Wl + woff + (size_t)(bn + lr) * K + lg;
    const uint32_t soff = (uint32_t)lr * ROWB + (tid & 1) * 16;

    float acc[4][4][4];
#pragma unroll
    for (int i = 0; i < 4; i++)
#pragma unroll
        for (int j = 0; j < 4; j++)
#pragma unroll
            for (int r = 0; r < 4; r++) acc[i][j][r] = 0.f;

    const int nch = K / 16;

#pragma unroll
    for (int c = 0; c < 3; c++) {
        const uint32_t sb = sbase + c * STAGE_B;
        const int k0 = c * 16;
        CP16(sb + T_AH + soff, pAh + k0);
        CP16(sb + T_AL + soff, pAl + k0);
        CP16(sb + T_BH + soff, pWh + k0);
        CP16(sb + T_BL + soff, pWl + k0);
        CP_COMMIT();
    }

    for (int c = 0; c < nch; c++) {
        CP_WAIT2();
        __syncthreads();

        if (c + 3 < nch) {
            const uint32_t sb = sbase + ((c + 3) & 3) * STAGE_B;
            const int k0 = (c + 3) * 16;
            CP16(sb + T_AH + soff, pAh + k0);
            CP16(sb + T_AL + soff, pAl + k0);
            CP16(sb + T_BH + soff, pWh + k0);
            CP16(sb + T_BL + soff, pWl + k0);
        }
        CP_COMMIT();

        const uint32_t stb = sbase + (c & 3) * STAGE_B;
        uint32_t ah[4][4], al[4][4];
#pragma unroll
        for (int mf = 0; mf < 4; mf++) {
            LDM4(ah[mf], stb + T_AH + a_off + mf * (16 * ROWB));
            LDM4(al[mf], stb + T_AL + a_off + mf * (16 * ROWB));
        }
        uint32_t bh[2][4], bl[2][4];
#pragma unroll
        for (int p = 0; p < 2; p++) {
            LDM4(bh[p], stb + T_BH + b_off + p * (16 * ROWB));
            LDM4(bl[p], stb + T_BL + b_off + p * (16 * ROWB));
        }
#pragma unroll
        for (int mf = 0; mf < 4; mf++) {
#pragma unroll
            for (int nf = 0; nf < 4; nf++) {
                const uint32_t b0h = bh[nf >> 1][(nf & 1) * 2];
                const uint32_t b1h = bh[nf >> 1][(nf & 1) * 2 + 1];
                const uint32_t b0l = bl[nf >> 1][(nf & 1) * 2];
                const uint32_t b1l = bl[nf >> 1][(nf & 1) * 2 + 1];
                MMA_BF16(acc[mf][nf], ah[mf], b0h, b1h);
                MMA_BF16(acc[mf][nf], ah[mf], b0l, b1l);
                MMA_BF16(acc[mf][nf], al[mf], b0h, b1h);
            }
        }
    }

    const int g  = lane >> 2;
    const int t2 = (lane & 3) * 2;
    const float sc = (SCALE_Q8 && bx < 8) ? 0.125f : 1.0f;
#pragma unroll
    for (int mf = 0; mf < 4; mf++) {
#pragma unroll
        for (int nf = 0; nf < 4; nf++) {
            const int m = bm + wm + mf * 16 + g;
            const int n = cn + wn + nf * 8 + t2;
            float2 v0, v1;
            v0.x = acc[mf][nf][0]; v0.y = acc[mf][nf][1];
            v1.x = acc[mf][nf][2]; v1.y = acc[mf][nf][3];
            if (OUT_BF16) {
                v0.x *= sc; v0.y *= sc; v1.x *= sc; v1.y *= sc;
                uint32_t l0_, l1_;
                uint32_t h0_ = hi_lo_pack(v0.x, v0.y, l0_);
                uint32_t h1_ = hi_lo_pack(v1.x, v1.y, l1_);
                *reinterpret_cast<uint32_t*>(&Ch[(size_t)m * ldc + n]) = h0_;
                *reinterpret_cast<uint32_t*>(&Cl[(size_t)m * ldc + n]) = l0_;
                *reinterpret_cast<uint32_t*>(&Ch[(size_t)(m + 8) * ldc + n]) = h1_;
                *reinterpret_cast<uint32_t*>(&Cl[(size_t)(m + 8) * ldc + n]) = l1_;
            } else {
                if (HAS_BIAS) {
                    const float2 bv = *reinterpret_cast<const float2*>(&bias[n]);
                    v0.x += bv.x; v0.y += bv.y;
                    v1.x += bv.x; v1.y += bv.y;
                }
                *reinterpret_cast<float2*>(&C[(size_t)m * ldc + n]) = v0;
                *reinterpret_cast<float2*>(&C[(size_t)(m + 8) * ldc + n]) = v1;
            }
        }
    }
}

// ===========================================================================
// Tensor-core causal flash attention, 4-stage cp.async KV ring
// (R10 MMA schedule, one extra prefetch stage).
// ===========================================================================
#define FROWB 144
#define KV_KH 0
#define KV_KL 9216
#define KV_VH 18432
#define KV_VL 27648
#define KV_STAGE 36864
#define SQH   0
#define SQL   18432
#define FLASH_SMEM_BYTES (4 * KV_STAGE)   // 147456

__global__ void __launch_bounds__(256) flash_mma(
    const __nv_bfloat16* __restrict__ qkvh,
    const __nv_bfloat16* __restrict__ qkvl,
    __nv_bfloat16* __restrict__ atth,
    __nv_bfloat16* __restrict__ attl)
{
    extern __shared__ __align__(128) char smem[];
    const uint32_t sbase = smem_u32(smem);
    const int tid  = threadIdx.x;
    const int lane = tid & 31;
    const int w    = tid >> 5;
    const int qt   = (gridDim.x - 1) - blockIdx.x;
    const int h    = blockIdx.y;
    const int b    = blockIdx.z;

    const size_t head_base = (size_t)b * S_LEN * QKV_LD + (size_t)h * HD;

    // ---- Stage Q hi/lo into stage0 area (consumed to regs before KV use) ----
    {
        const int r = tid >> 1;
        const int g0 = (tid & 1) * 4;
        const __nv_bfloat16* qrh = qkvh + head_base + (size_t)(qt * 128 + r) * QKV_LD;
        const __nv_bfloat16* qrl = qkvl + head_base + (size_t)(qt * 128 + r) * QKV_LD;
#pragma unroll
        for (int t = 0; t < 4; t++) {
            const int gg = g0 + t;
            const uint32_t off = (uint32_t)r * FROWB + gg * 16;
            *reinterpret_cast<uint4*>(smem + SQH + off) =
                *reinterpret_cast<const uint4*>(qrh + gg * 8);
            *reinterpret_cast<uint4*>(smem + SQL + off) =
                *reinterpret_cast<const uint4*>(qrl + gg * 8);
        }
    }
    __syncthreads();

    uint32_t qh[4][4], ql[4][4];
    {
        const uint32_t a_off = (uint32_t)(w * 16 + (lane & 15)) * FROWB
                               + ((lane >> 4) * 8) * 2;
#pragma unroll
        for (int ks = 0; ks < 4; ks++) {
            LDM4(qh[ks], sbase + SQH + a_off + ks * 32);
            LDM4(ql[ks], sbase + SQL + a_off + ks * 32);
        }
    }
    __syncthreads();

    float o[8][4];
#pragma unroll
    for (int nf = 0; nf < 8; nf++)
#pragma unroll
        for (int r = 0; r < 4; r++) o[nf][r] = 0.f;
    float m0 = -1e30f, m1 = -1e30f, l0 = 0.f, l1 = 0.f;

    const int g  = lane >> 2;
    const int t2 = (lane & 3) * 2;
    const int wrow = qt * 128 + w * 16;
    const int row0 = wrow + g;
    const int row1 = row0 + 8;

    const uint32_t kb_off = (uint32_t)((lane >> 4) * 8 + (lane & 7)) * FROWB
                            + (((lane >> 3) & 1) * 8) * 2;
    const uint32_t vt_row = (uint32_t)(lane & 15) * FROWB + ((lane >> 4) * 8) * 2;

    const int klr = tid >> 2;
    const int kg0 = (tid & 3) * 2;

    const int kt_end = 2 * qt + 1;   // >= 1

    // prologue: kt=0,1,2 -> buffers 0,1,2 (kt=2 rows < 192 always in-range)
#pragma unroll
    for (int c = 0; c < 3; c++) {
        const uint32_t sb = sbase + c * KV_STAGE;
        const size_t rowb = head_base + (size_t)(c * 64 + klr) * QKV_LD;
#pragma unroll
        for (int t = 0; t < 2; t++) {
            const int gg = kg0 + t;
            const uint32_t off = (uint32_t)klr * FROWB + gg * 16;
            CP16(sb + KV_KH + off, qkvh + rowb + D_MODEL + gg * 8);
            CP16(sb + KV_KL + off, qkvl + rowb + D_MODEL + gg * 8);
            CP16(sb + KV_VH + off, qkvh + rowb + 2 * D_MODEL + gg * 8);
            CP16(sb + KV_VL + off, qkvl + rowb + 2 * D_MODEL + gg * 8);
        }
        CP_COMMIT();
    }

    for (int kt = 0; kt <= kt_end; kt++) {
        CP_WAIT2();
        __syncthreads();

        // issue kt+3 into buffer (kt+3)&3 (kt-1's buffer; compute done)
        if (kt + 3 <= kt_end) {
            const uint32_t sb = sbase + ((kt + 3) & 3) * KV_STAGE;
            const size_t rowb = head_base + (size_t)((kt + 3) * 64 + klr) * QKV_LD;
#pragma unroll
            for (int t = 0; t < 2; t++) {
                const int gg = kg0 + t;
                const uint32_t off = (uint32_t)klr * FROWB + gg * 16;
                CP16(sb + KV_KH + off, qkvh + rowb + D_MODEL + gg * 8);
                CP16(sb + KV_KL + off, qkvl + rowb + D_MODEL + gg * 8);
                CP16(sb + KV_VH + off, qkvh + rowb + 2 * D_MODEL + gg * 8);
                CP16(sb + KV_VL + off, qkvl + rowb + 2 * D_MODEL + gg * 8);
            }
        }
        CP_COMMIT();   // uniform commit keeps wait_group arithmetic exact

        const bool active = (kt * 64 <= wrow + 15);
        if (active) {
            const uint32_t stb = sbase + (kt & 3) * KV_STAGE;
            float s[8][4];
#pragma unroll
            for (int nf = 0; nf < 8; nf++)
#pragma unroll
                for (int r = 0; r < 4; r++) s[nf][r] = 0.f;

#pragma unroll
            for (int ks = 0; ks < 4; ks++) {
#pragma unroll
                for (int p = 0; p < 4; p++) {
                    uint32_t kh[4], kl[4];
                    LDM4(kh, stb + KV_KH + kb_off + p * (16 * FROWB) + ks * 32);
                    LDM4(kl, stb + KV_KL + kb_off + p * (16 * FROWB) + ks * 32);
                    MMA_BF16(s[2 * p],     qh[ks], kh[0], kh[1]);
                    MMA_BF16(s[2 * p],     qh[ks], kl[0], kl[1]);
                    MMA_BF16(s[2 * p],     ql[ks], kh[0], kh[1]);
                    MMA_BF16(s[2 * p + 1], qh[ks], kh[2], kh[3]);
                    MMA_BF16(s[2 * p + 1], qh[ks], kl[2], kl[3]);
                    MMA_BF16(s[2 * p + 1], ql[ks], kh[2], kh[3]);
                }
            }

            if (kt * 64 + 63 > wrow) {
#pragma unroll
                for (int nf = 0; nf < 8; nf++) {
                    const int c0 = kt * 64 + nf * 8 + t2;
                    if (c0     > row0) s[nf][0] = -1e30f;
                    if (c0 + 1 > row0) s[nf][1] = -1e30f;
                    if (c0     > row1) s[nf][2] = -1e30f;
                    if (c0 + 1 > row1) s[nf][3] = -1e30f;
                }
            }

            float mx0 = s[0][0], mx1 = s[0][2];
#pragma unroll
            for (int nf = 0; nf < 8; nf++) {
                mx0 = fmaxf(mx0, fmaxf(s[nf][0], s[nf][1]));
                mx1 = fmaxf(mx1, fmaxf(s[nf][2], s[nf][3]));
            }
            mx0 = fmaxf(mx0, __shfl_xor_sync(0xffffffffu, mx0, 1));
            mx0 = fmaxf(mx0, __shfl_xor_sync(0xffffffffu, mx0, 2));
            mx1 = fmaxf(mx1, __shfl_xor_sync(0xffffffffu, mx1, 1));
            mx1 = fmaxf(mx1, __shfl_xor_sync(0xffffffffu, mx1, 2));

            const float nm0 = fmaxf(m0, mx0), nm1 = fmaxf(m1, mx1);
            const float a0 = __expf(m0 - nm0), a1 = __expf(m1 - nm1);
            m0 = nm0; m1 = nm1;

            float sum0 = 0.f, sum1 = 0.f;
#pragma unroll
            for (int nf = 0; nf < 8; nf++) {
                s[nf][0] = __expf(s[nf][0] - nm0);
                s[nf][1] = __expf(s[nf][1] - nm0);
                s[nf][2] = __expf(s[nf][2] - nm1);
                s[nf][3] = __expf(s[nf][3] - nm1);
                sum0 += s[nf][0] + s[nf][1];
                sum1 += s[nf][2] + s[nf][3];
            }
            sum0 += __shfl_xor_sync(0xffffffffu, sum0, 1);
            sum0 += __shfl_xor_sync(0xffffffffu, sum0, 2);
            sum1 += __shfl_xor_sync(0xffffffffu, sum1, 1);
            sum1 += __shfl_xor_sync(0xffffffffu, sum1, 2);
            l0 = l0 * a0 + sum0;
            l1 = l1 * a1 + sum1;

#pragma unroll
            for (int nf = 0; nf < 8; nf++) {
                o[nf][0] *= a0; o[nf][1] *= a0;
                o[nf][2] *= a1; o[nf][3] *= a1;
            }

#pragma unroll
            for (int j = 0; j < 4; j++) {
                uint32_t ph[4], pl[4];
                ph[0] = hi_lo_pack(s[2 * j][0],     s[2 * j][1],     pl[0]);
                ph[1] = hi_lo_pack(s[2 * j][2],     s[2 * j][3],     pl[1]);
                ph[2] = hi_lo_pack(s[2 * j + 1][0], s[2 * j + 1][1], pl[2]);
                ph[3] = hi_lo_pack(s[2 * j + 1][2], s[2 * j + 1][3], pl[3]);

                const uint32_t vbase = (uint32_t)(j * 16) * FROWB + vt_row;
#pragma unroll
                for (int hg = 0; hg < 4; hg++) {
                    uint32_t vh[4], vl[4];
                    LDM4T(vh, stb + KV_VH + vbase + hg * 32);
                    LDM4T(vl, stb + KV_VL + vbase + hg * 32);
                    MMA_BF16(o[2 * hg],     ph, vh[0], vh[1]);
                    MMA_BF16(o[2 * hg],     ph, vl[0], vl[1]);
                    MMA_BF16(o[2 * hg],     pl, vh[0], vh[1]);
                    MMA_BF16(o[2 * hg + 1], ph, vh[2], vh[3]);
                    MMA_BF16(o[2 * hg + 1], ph, vl[2], vl[3]);
                    MMA_BF16(o[2 * hg + 1], pl, vh[2], vh[3]);
                }
            }
        }
    }

    const float inv0 = 1.f / l0, inv1 = 1.f / l1;
    const size_t ob = ((size_t)b * S_LEN + qt * 128 + w * 16) * D_MODEL
                      + (size_t)h * HD;
#pragma unroll
    for (int nf = 0; nf < 8; nf++) {
        const int c = nf * 8 + t2;
        uint32_t lo0, lo1;
        uint32_t hi0 = hi_lo_pack(o[nf][0] * inv0, o[nf][1] * inv0, lo0);
        uint32_t hi1 = hi_lo_pack(o[nf][2] * inv1, o[nf][3] * inv1, lo1);
        *reinterpret_cast<uint32_t*>(&atth[ob + (size_t)g * D_MODEL + c]) = hi0;
        *reinterpret_cast<uint32_t*>(&attl[ob + (size_t)g * D_MODEL + c]) = lo0;
        *reinterpret_cast<uint32_t*>(&atth[ob + (size_t)(g + 8) * D_MODEL + c]) = hi1;
        *reinterpret_cast<uint32_t*>(&attl[ob + (size_t)(g + 8) * D_MODEL + c]) = lo1;
    }
}

// ---------------------------------------------------------------------------
extern "C" void kernel_launch(void* const* d_in, const int* in_sizes, int n_in,
                              void* d_out, int out_size)
{
    const float* x    = (const float*)d_in[0];
    const float* wq   = (const float*)d_in[1];
    const float* wk   = (const float*)d_in[2];
    const float* wv   = (const float*)d_in[3];
    const float* wo_w = (const float*)d_in[4];
    const float* wo_b = (const float*)d_in[5];
    float* out = (float*)d_out;

    __nv_bfloat16 *xh, *xl, *wh, *wl, *woh, *wol, *qkvh, *qkvl, *atth, *attl;
    cudaGetSymbolAddress((void**)&xh,   g_xh);
    cudaGetSymbolAddress((void**)&xl,   g_xl);
    cudaGetSymbolAddress((void**)&wh,   g_wh);
    cudaGetSymbolAddress((void**)&wl,   g_wl);
    cudaGetSymbolAddress((void**)&woh,  g_woh);
    cudaGetSymbolAddress((void**)&wol,  g_wol);
    cudaGetSymbolAddress((void**)&qkvh, g_qkvh);
    cudaGetSymbolAddress((void**)&qkvl, g_qkvl);
    cudaGetSymbolAddress((void**)&atth, g_atth);
    cudaGetSymbolAddress((void**)&attl, g_attl);

    static bool attr_done = false;
    if (!attr_done) {
        cudaFuncSetAttribute((const void*)mma_gemm<false, true, true>,
                             cudaFuncAttributeMaxDynamicSharedMemorySize,
                             GEMM_SMEM_BYTES);
        cudaFuncSetAttribute((const void*)mma_gemm<true, false, false>,
                             cudaFuncAttributeMaxDynamicSharedMemorySize,
                             GEMM_SMEM_BYTES);
        cudaFuncSetAttribute((const void*)flash_mma,
                             cudaFuncAttributeMaxDynamicSharedMemorySize,
                             FLASH_SMEM_BYTES);
        attr_done = true;
    }

    const int total4 = XF4 + 4 * WF4;
    cvt_all<<<(total4 + 255) / 256, 256>>>(x, wq, wk, wv, wo_w,
                                           xh, xl, wh, wl, woh, wol);

    const dim3 qkv_grid(24, M_ROWS / 128);
    mma_gemm<false, true, true><<<qkv_grid, 256, GEMM_SMEM_BYTES>>>(
        xh, xl, wh, wl, nullptr, nullptr, qkvh, qkvl, D_MODEL, QKV_LD);

    const dim3 flash_grid(S_LEN / 128, NHEAD, B_SZ);
    flash_mma<<<flash_grid, 256, FLASH_SMEM_BYTES>>>(qkvh, qkvl, atth, attl);

    const dim3 o_grid(8, M_ROWS / 128);
    mma_gemm<true, false, false><<<o_grid, 256, GEMM_SMEM_BYTES>>>(
        atth, attl, woh, wol, wo_b, out, nullptr, nullptr, D_MODEL, D_MODEL);
}

// round 13
// speedup vs baseline: 1.1775x; 1.0990x over previous
#include <cuda_runtime.h>
#include <cuda_bf16.h>
#include <cuda_fp16.h>
#include <cstdint>

#define B_SZ    2
#define S_LEN   2048
#define D_MODEL 1024
#define NHEAD   16
#define HD      64
#define M_ROWS  (B_SZ * S_LEN)      // 4096
#define QKV_LD  (3 * D_MODEL)       // 3072
#define DSQ     (D_MODEL * D_MODEL) // 1048576

// scratch (device globals)
__device__ __nv_bfloat16 g_xh [(size_t)M_ROWS * D_MODEL];
__device__ __nv_bfloat16 g_xl [(size_t)M_ROWS * D_MODEL];
__device__ __nv_bfloat16 g_wh [(size_t)3 * DSQ];               // wq|wk|wv
__device__ __nv_bfloat16 g_wl [(size_t)3 * DSQ];
__device__ __nv_bfloat16 g_woh[(size_t)DSQ];
__device__ __nv_bfloat16 g_wol[(size_t)DSQ];
__device__ __half        g_qkvh[(size_t)M_ROWS * QKV_LD];      // fp16 hi: Q(x0.125)|K|V
__device__ __half        g_qkvl[(size_t)M_ROWS * QKV_LD];      // fp16 lo (only Q used)
__device__ __nv_bfloat16 g_atth[(size_t)M_ROWS * D_MODEL];
__device__ __nv_bfloat16 g_attl[(size_t)M_ROWS * D_MODEL];

__device__ __forceinline__ uint32_t smem_u32(const void* p) {
    uint32_t a;
    asm("{ .reg .u64 t; cvta.to.shared.u64 t, %1; cvt.u32.u64 %0, t; }"
        : "=r"(a) : "l"(p));
    return a;
}

#define LDM4(r, addr) \
    asm volatile("ldmatrix.sync.aligned.m8n8.x4.shared.b16 {%0,%1,%2,%3}, [%4];" \
        : "=r"((r)[0]), "=r"((r)[1]), "=r"((r)[2]), "=r"((r)[3]) : "r"(addr))

#define LDM4T(r, addr) \
    asm volatile("ldmatrix.sync.aligned.m8n8.x4.trans.shared.b16 {%0,%1,%2,%3}, [%4];" \
        : "=r"((r)[0]), "=r"((r)[1]), "=r"((r)[2]), "=r"((r)[3]) : "r"(addr))

#define MMA_BF16(d, a, b0, b1) \
    asm volatile("mma.sync.aligned.m16n8k16.row.col.f32.bf16.bf16.f32 " \
        "{%0,%1,%2,%3}, {%4,%5,%6,%7}, {%8,%9}, {%0,%1,%2,%3};" \
        : "+f"((d)[0]), "+f"((d)[1]), "+f"((d)[2]), "+f"((d)[3]) \
        : "r"((a)[0]), "r"((a)[1]), "r"((a)[2]), "r"((a)[3]), "r"(b0), "r"(b1))

#define MMA_F16(d, a, b0, b1) \
    asm volatile("mma.sync.aligned.m16n8k16.row.col.f32.f16.f16.f32 " \
        "{%0,%1,%2,%3}, {%4,%5,%6,%7}, {%8,%9}, {%0,%1,%2,%3};" \
        : "+f"((d)[0]), "+f"((d)[1]), "+f"((d)[2]), "+f"((d)[3]) \
        : "r"((a)[0]), "r"((a)[1]), "r"((a)[2]), "r"((a)[3]), "r"(b0), "r"(b1))

#define CP16(dst, src) \
    asm volatile("cp.async.cg.shared.global [%0], [%1], 16;" \
        :: "r"(dst), "l"(src) : "memory")
#define CP_COMMIT() asm volatile("cp.async.commit_group;" ::: "memory")
#define CP_WAIT2()  asm volatile("cp.async.wait_group 2;" ::: "memory")

__device__ __forceinline__ uint32_t pack2(__nv_bfloat16 a, __nv_bfloat16 b) {
    return (uint32_t)__bfloat16_as_ushort(a) |
           ((uint32_t)__bfloat16_as_ushort(b) << 16);
}
__device__ __forceinline__ uint32_t pack2h(__half a, __half b) {
    return (uint32_t)__half_as_ushort(a) |
           ((uint32_t)__half_as_ushort(b) << 16);
}

__device__ __forceinline__ void cvt4(float4 v, uint2& h, uint2& l) {
    __nv_bfloat16 h0 = __float2bfloat16_rn(v.x);
    __nv_bfloat16 h1 = __float2bfloat16_rn(v.y);
    __nv_bfloat16 h2 = __float2bfloat16_rn(v.z);
    __nv_bfloat16 h3 = __float2bfloat16_rn(v.w);
    __nv_bfloat16 l0 = __float2bfloat16_rn(v.x - __bfloat162float(h0));
    __nv_bfloat16 l1 = __float2bfloat16_rn(v.y - __bfloat162float(h1));
    __nv_bfloat16 l2 = __float2bfloat16_rn(v.z - __bfloat162float(h2));
    __nv_bfloat16 l3 = __float2bfloat16_rn(v.w - __bfloat162float(h3));
    h.x = pack2(h0, h1); h.y = pack2(h2, h3);
    l.x = pack2(l0, l1); l.y = pack2(l2, l3);
}

__device__ __forceinline__ uint32_t hi_lo_pack(float a, float b, uint32_t& lo) {
    __nv_bfloat16 ha = __float2bfloat16_rn(a);
    __nv_bfloat16 hb = __float2bfloat16_rn(b);
    lo = pack2(__float2bfloat16_rn(a - __bfloat162float(ha)),
               __float2bfloat16_rn(b - __bfloat162float(hb)));
    return pack2(ha, hb);
}

__device__ __forceinline__ uint32_t hi_lo_pack_f16(float a, float b, uint32_t& lo) {
    __half ha = __float2half_rn(a);
    __half hb = __float2half_rn(b);
    lo = pack2h(__float2half_rn(a - __half2float(ha)),
                __float2half_rn(b - __half2float(hb)));
    return pack2h(ha, hb);
}

// ---------------------------------------------------------------------------
// Fused one-shot f32 -> bf16 hi/lo conversion of all five tensors
// ---------------------------------------------------------------------------
#define XF4 (M_ROWS * D_MODEL / 4)
#define WF4 (DSQ / 4)

__global__ void cvt_all(
    const float* __restrict__ x,  const float* __restrict__ wq,
    const float* __restrict__ wk, const float* __restrict__ wv,
    const float* __restrict__ wo,
    __nv_bfloat16* __restrict__ xh,  __nv_bfloat16* __restrict__ xl,
    __nv_bfloat16* __restrict__ wh,  __nv_bfloat16* __restrict__ wl,
    __nv_bfloat16* __restrict__ woh, __nv_bfloat16* __restrict__ wol)
{
    const int i = blockIdx.x * blockDim.x + threadIdx.x;
    const float* src; __nv_bfloat16 *oh, *ol; int j;
    if (i < XF4)              { src = x;  oh = xh;  ol = xl;  j = i; }
    else if (i < XF4 + WF4)   { src = wq; oh = wh;  ol = wl;  j = i - XF4; }
    else if (i < XF4 + 2*WF4) { src = wk; oh = wh + DSQ;  ol = wl + DSQ;  j = i - XF4 - WF4; }
    else if (i < XF4 + 3*WF4) { src = wv; oh = wh + 2*DSQ; ol = wl + 2*DSQ; j = i - XF4 - 2*WF4; }
    else if (i < XF4 + 4*WF4) { src = wo; oh = woh; ol = wol; j = i - XF4 - 3*WF4; }
    else return;
    float4 v = reinterpret_cast<const float4*>(src)[j];
    uint2 hh, ll;
    cvt4(v, hh, ll);
    reinterpret_cast<uint2*>(oh)[j] = hh;
    reinterpret_cast<uint2*>(ol)[j] = ll;
}

// ===========================================================================
// mma.sync bf16x3 GEMM (R12-verified). OUT_F16: write fp16 hi/lo (+Q scale).
// ===========================================================================
#define ROWB    48
#define T_AH    0
#define T_AL    6144
#define T_BH    12288
#define T_BL    18432
#define STAGE_B 24576
#define GEMM_SMEM_BYTES (4 * STAGE_B)  // 98304

template <bool HAS_BIAS, bool OUT_F16, bool SCALE_Q8>
__global__ void __launch_bounds__(256, 2) mma_gemm(
    const __nv_bfloat16* __restrict__ Ah, const __nv_bfloat16* __restrict__ Al,
    const __nv_bfloat16* __restrict__ Wh, const __nv_bfloat16* __restrict__ Wl,
    const float* __restrict__ bias,
    float* __restrict__ C,
    __half* __restrict__ Ch, __half* __restrict__ Cl,
    int K, int ldc)
{
    extern __shared__ __align__(128) char smem[];
    const uint32_t sbase = smem_u32(smem);
    const int tid  = threadIdx.x;
    const int lane = tid & 31;
    const int bx   = blockIdx.x;
    const int bm   = blockIdx.y * 128;
    const int bn   = (bx & 7) * 128;
    const int cn   = (bx >> 3) * D_MODEL + bn;
    const size_t woff = (size_t)(bx >> 3) * DSQ;

    const int wm = (tid >> 7) * 64;
    const int wn = ((tid >> 5) & 3) * 32;

    const uint32_t a_off = (uint32_t)(wm + (lane & 15)) * ROWB + (lane >> 4) * 16;
    const uint32_t b_off = (uint32_t)(wn + (lane >> 4) * 8 + (lane & 7)) * ROWB
                           + ((lane >> 3) & 1) * 16;

    const int lr = tid >> 1;
    const int lg = (tid & 1) * 8;
    const __nv_bfloat16* pAh = Ah + (size_t)(bm + lr) * K + lg;
    const __nv_bfloat16* pAl = Al + (size_t)(bm + lr) * K + lg;
    const __nv_bfloat16* pWh = Wh + woff + (size_t)(bn + lr) * K + lg;
    const __nv_bfloat16* pWl = Wl + woff + (size_t)(bn + lr) * K + lg;
    const uint32_t soff = (uint32_t)lr * ROWB + (tid & 1) * 16;

    float acc[4][4][4];
#pragma unroll
    for (int i = 0; i < 4; i++)
#pragma unroll
        for (int j = 0; j < 4; j++)
#pragma unroll
            for (int r = 0; r < 4; r++) acc[i][j][r] = 0.f;

    const int nch = K / 16;

#pragma unroll
    for (int c = 0; c < 3; c++) {
        const uint32_t sb = sbase + c * STAGE_B;
        const int k0 = c * 16;
        CP16(sb + T_AH + soff, pAh + k0);
        CP16(sb + T_AL + soff, pAl + k0);
        CP16(sb + T_BH + soff, pWh + k0);
        CP16(sb + T_BL + soff, pWl + k0);
        CP_COMMIT();
    }

    for (int c = 0; c < nch; c++) {
        CP_WAIT2();
        __syncthreads();

        if (c + 3 < nch) {
            const uint32_t sb = sbase + ((c + 3) & 3) * STAGE_B;
            const int k0 = (c + 3) * 16;
            CP16(sb + T_AH + soff, pAh + k0);
            CP16(sb + T_AL + soff, pAl + k0);
            CP16(sb + T_BH + soff, pWh + k0);
            CP16(sb + T_BL + soff, pWl + k0);
        }
        CP_COMMIT();

        const uint32_t stb = sbase + (c & 3) * STAGE_B;
        uint32_t ah[4][4], al[4][4];
#pragma unroll
        for (int mf = 0; mf < 4; mf++) {
            LDM4(ah[mf], stb + T_AH + a_off + mf * (16 * ROWB));
            LDM4(al[mf], stb + T_AL + a_off + mf * (16 * ROWB));
        }
        uint32_t bh[2][4], bl[2][4];
#pragma unroll
        for (int p = 0; p < 2; p++) {
            LDM4(bh[p], stb + T_BH + b_off + p * (16 * ROWB));
            LDM4(bl[p], stb + T_BL + b_off + p * (16 * ROWB));
        }
#pragma unroll
        for (int mf = 0; mf < 4; mf++) {
#pragma unroll
            for (int nf = 0; nf < 4; nf++) {
                const uint32_t b0h = bh[nf >> 1][(nf & 1) * 2];
                const uint32_t b1h = bh[nf >> 1][(nf & 1) * 2 + 1];
                const uint32_t b0l = bl[nf >> 1][(nf & 1) * 2];
                const uint32_t b1l = bl[nf >> 1][(nf & 1) * 2 + 1];
                MMA_BF16(acc[mf][nf], ah[mf], b0h, b1h);
                MMA_BF16(acc[mf][nf], ah[mf], b0l, b1l);
                MMA_BF16(acc[mf][nf], al[mf], b0h, b1h);
            }
        }
    }

    const int g  = lane >> 2;
    const int t2 = (lane & 3) * 2;
    const float sc = (SCALE_Q8 && bx < 8) ? 0.125f : 1.0f;
#pragma unroll
    for (int mf = 0; mf < 4; mf++) {
#pragma unroll
        for (int nf = 0; nf < 4; nf++) {
            const int m = bm + wm + mf * 16 + g;
            const int n = cn + wn + nf * 8 + t2;
            float2 v0, v1;
            v0.x = acc[mf][nf][0]; v0.y = acc[mf][nf][1];
            v1.x = acc[mf][nf][2]; v1.y = acc[mf][nf][3];
            if (OUT_F16) {
                v0.x *= sc; v0.y *= sc; v1.x *= sc; v1.y *= sc;
                uint32_t l0_, l1_;
                uint32_t h0_ = hi_lo_pack_f16(v0.x, v0.y, l0_);
                uint32_t h1_ = hi_lo_pack_f16(v1.x, v1.y, l1_);
                *reinterpret_cast<uint32_t*>(&Ch[(size_t)m * ldc + n]) = h0_;
                *reinterpret_cast<uint32_t*>(&Cl[(size_t)m * ldc + n]) = l0_;
                *reinterpret_cast<uint32_t*>(&Ch[(size_t)(m + 8) * ldc + n]) = h1_;
                *reinterpret_cast<uint32_t*>(&Cl[(size_t)(m + 8) * ldc + n]) = l1_;
            } else {
                if (HAS_BIAS) {
                    const float2 bv = *reinterpret_cast<const float2*>(&bias[n]);
                    v0.x += bv.x; v0.y += bv.y;
                    v1.x += bv.x; v1.y += bv.y;
                }
                *reinterpret_cast<float2*>(&C[(size_t)m * ldc + n]) = v0;
                *reinterpret_cast<float2*>(&C[(size_t)(m + 8) * ldc + n]) = v1;
            }
        }
    }
}

// ===========================================================================
// fp16 tensor-core causal flash attention, 4-stage cp.async KV ring.
// Q: fp16 hi/lo (in regs). K,V: SINGLE fp16. P: fp16 hi/lo (in regs).
// QK = QhK + QlK (2 mma); PV = PhV + PlV (2 mma). 128 MMAs/tile.
// ===========================================================================
#define FROWB 144
#define KV_K  0
#define KV_V  9216
#define KV_STAGE 18432
#define SQH   0
#define SQL   18432
#define FLASH_SMEM_BYTES (4 * KV_STAGE)   // 73728

__global__ void __launch_bounds__(256) flash_mma(
    const __half* __restrict__ qkvh,
    const __half* __restrict__ qkvl,
    __nv_bfloat16* __restrict__ atth,
    __nv_bfloat16* __restrict__ attl)
{
    extern __shared__ __align__(128) char smem[];
    const uint32_t sbase = smem_u32(smem);
    const int tid  = threadIdx.x;
    const int lane = tid & 31;
    const int w    = tid >> 5;
    const int qt   = (gridDim.x - 1) - blockIdx.x;
    const int h    = blockIdx.y;
    const int b    = blockIdx.z;

    const size_t head_base = (size_t)b * S_LEN * QKV_LD + (size_t)h * HD;

    // ---- Stage Q hi/lo (fp16), consume to registers ----
    {
        const int r = tid >> 1;
        const int g0 = (tid & 1) * 4;
        const __half* qrh = qkvh + head_base + (size_t)(qt * 128 + r) * QKV_LD;
        const __half* qrl = qkvl + head_base + (size_t)(qt * 128 + r) * QKV_LD;
#pragma unroll
        for (int t = 0; t < 4; t++) {
            const int gg = g0 + t;
            const uint32_t off = (uint32_t)r * FROWB + gg * 16;
            *reinterpret_cast<uint4*>(smem + SQH + off) =
                *reinterpret_cast<const uint4*>(qrh + gg * 8);
            *reinterpret_cast<uint4*>(smem + SQL + off) =
                *reinterpret_cast<const uint4*>(qrl + gg * 8);
        }
    }
    __syncthreads();

    uint32_t qh[4][4], ql[4][4];
    {
        const uint32_t a_off = (uint32_t)(w * 16 + (lane & 15)) * FROWB
                               + ((lane >> 4) * 8) * 2;
#pragma unroll
        for (int ks = 0; ks < 4; ks++) {
            LDM4(qh[ks], sbase + SQH + a_off + ks * 32);
            LDM4(ql[ks], sbase + SQL + a_off + ks * 32);
        }
    }
    __syncthreads();

    float o[8][4];
#pragma unroll
    for (int nf = 0; nf < 8; nf++)
#pragma unroll
        for (int r = 0; r < 4; r++) o[nf][r] = 0.f;
    float m0 = -1e30f, m1 = -1e30f, l0 = 0.f, l1 = 0.f;

    const int g  = lane >> 2;
    const int t2 = (lane & 3) * 2;
    const int wrow = qt * 128 + w * 16;
    const int row0 = wrow + g;
    const int row1 = row0 + 8;

    const uint32_t kb_off = (uint32_t)((lane >> 4) * 8 + (lane & 7)) * FROWB
                            + (((lane >> 3) & 1) * 8) * 2;
    const uint32_t vt_row = (uint32_t)(lane & 15) * FROWB + ((lane >> 4) * 8) * 2;

    const int klr = tid >> 2;            // row 0..63
    const int kg0 = (tid & 3) * 2;       // granule base (2 granules each of 8)

    const int kt_end = 2 * qt + 1;

    // prologue: kt=0,1,2 -> buffers 0,1,2
#pragma unroll
    for (int c = 0; c < 3; c++) {
        const uint32_t sb = sbase + c * KV_STAGE;
        const size_t rowb = head_base + (size_t)(c * 64 + klr) * QKV_LD;
#pragma unroll
        for (int t = 0; t < 2; t++) {
            const int gg = kg0 + t;
            const uint32_t off = (uint32_t)klr * FROWB + gg * 16;
            CP16(sb + KV_K + off, qkvh + rowb + D_MODEL + gg * 8);
            CP16(sb + KV_V + off, qkvh + rowb + 2 * D_MODEL + gg * 8);
        }
        CP_COMMIT();
    }

    for (int kt = 0; kt <= kt_end; kt++) {
        CP_WAIT2();
        __syncthreads();

        if (kt + 3 <= kt_end) {
            const uint32_t sb = sbase + ((kt + 3) & 3) * KV_STAGE;
            const size_t rowb = head_base + (size_t)((kt + 3) * 64 + klr) * QKV_LD;
#pragma unroll
            for (int t = 0; t < 2; t++) {
                const int gg = kg0 + t;
                const uint32_t off = (uint32_t)klr * FROWB + gg * 16;
                CP16(sb + KV_K + off, qkvh + rowb + D_MODEL + gg * 8);
                CP16(sb + KV_V + off, qkvh + rowb + 2 * D_MODEL + gg * 8);
            }
        }
        CP_COMMIT();

        const bool active = (kt * 64 <= wrow + 15);
        if (active) {
            const uint32_t stb = sbase + (kt & 3) * KV_STAGE;
            float s[8][4];
#pragma unroll
            for (int nf = 0; nf < 8; nf++)
#pragma unroll
                for (int r = 0; r < 4; r++) s[nf][r] = 0.f;

#pragma unroll
            for (int ks = 0; ks < 4; ks++) {
#pragma unroll
                for (int p = 0; p < 4; p++) {
                    uint32_t kh[4];
                    LDM4(kh, stb + KV_K + kb_off + p * (16 * FROWB) + ks * 32);
                    MMA_F16(s[2 * p],     qh[ks], kh[0], kh[1]);
                    MMA_F16(s[2 * p + 1], qh[ks], kh[2], kh[3]);
                    MMA_F16(s[2 * p],     ql[ks], kh[0], kh[1]);
                    MMA_F16(s[2 * p + 1], ql[ks], kh[2], kh[3]);
                }
            }

            if (kt * 64 + 63 > wrow) {
#pragma unroll
                for (int nf = 0; nf < 8; nf++) {
                    const int c0 = kt * 64 + nf * 8 + t2;
                    if (c0     > row0) s[nf][0] = -1e30f;
                    if (c0 + 1 > row0) s[nf][1] = -1e30f;
                    if (c0     > row1) s[nf][2] = -1e30f;
                    if (c0 + 1 > row1) s[nf][3] = -1e30f;
                }
            }

            float mx0 = s[0][0], mx1 = s[0][2];
#pragma unroll
            for (int nf = 0; nf < 8; nf++) {
                mx0 = fmaxf(mx0, fmaxf(s[nf][0], s[nf][1]));
                mx1 = fmaxf(mx1, fmaxf(s[nf][2], s[nf][3]));
            }
            mx0 = fmaxf(mx0, __shfl_xor_sync(0xffffffffu, mx0, 1));
            mx0 = fmaxf(mx0, __shfl_xor_sync(0xffffffffu, mx0, 2));
            mx1 = fmaxf(mx1, __shfl_xor_sync(0xffffffffu, mx1, 1));
            mx1 = fmaxf(mx1, __shfl_xor_sync(0xffffffffu, mx1, 2));

            const float nm0 = fmaxf(m0, mx0), nm1 = fmaxf(m1, mx1);
            const float a0 = __expf(m0 - nm0), a1 = __expf(m1 - nm1);
            m0 = nm0; m1 = nm1;

            float sum0 = 0.f, sum1 = 0.f;
#pragma unroll
            for (int nf = 0; nf < 8; nf++) {
                s[nf][0] = __expf(s[nf][0] - nm0);
                s[nf][1] = __expf(s[nf][1] - nm0);
                s[nf][2] = __expf(s[nf][2] - nm1);
                s[nf][3] = __expf(s[nf][3] - nm1);
                sum0 += s[nf][0] + s[nf][1];
                sum1 += s[nf][2] + s[nf][3];
            }
            sum0 += __shfl_xor_sync(0xffffffffu, sum0, 1);
            sum0 += __shfl_xor_sync(0xffffffffu, sum0, 2);
            sum1 += __shfl_xor_sync(0xffffffffu, sum1, 1);
            sum1 += __shfl_xor_sync(0xffffffffu, sum1, 2);
            l0 = l0 * a0 + sum0;
            l1 = l1 * a1 + sum1;

#pragma unroll
            for (int nf = 0; nf < 8; nf++) {
                o[nf][0] *= a0; o[nf][1] *= a0;
                o[nf][2] *= a1; o[nf][3] *= a1;
            }

#pragma unroll
            for (int j = 0; j < 4; j++) {
                uint32_t ph[4], pl[4];
                ph[0] = hi_lo_pack_f16(s[2 * j][0],     s[2 * j][1],     pl[0]);
                ph[1] = hi_lo_pack_f16(s[2 * j][2],     s[2 * j][3],     pl[1]);
                ph[2] = hi_lo_pack_f16(s[2 * j + 1][0], s[2 * j + 1][1], pl[2]);
                ph[3] = hi_lo_pack_f16(s[2 * j + 1][2], s[2 * j + 1][3], pl[3]);

                const uint32_t vbase = (uint32_t)(j * 16) * FROWB + vt_row;
#pragma unroll
                for (int hg = 0; hg < 4; hg++) {
                    uint32_t vh[4];
                    LDM4T(vh, stb + KV_V + vbase + hg * 32);
                    MMA_F16(o[2 * hg],     ph, vh[0], vh[1]);
                    MMA_F16(o[2 * hg + 1], ph, vh[2], vh[3]);
                    MMA_F16(o[2 * hg],     pl, vh[0], vh[1]);
                    MMA_F16(o[2 * hg + 1], pl, vh[2], vh[3]);
                }
            }
        }
    }

    // ---- Normalize and write attn as bf16 hi/lo (for bf16x3 O-proj) ----
    const float inv0 = 1.f / l0, inv1 = 1.f / l1;
    const size_t ob = ((size_t)b * S_LEN + qt * 128 + w * 16) * D_MODEL
                      + (size_t)h * HD;
#pragma unroll
    for (int nf = 0; nf < 8; nf++) {
        const int c = nf * 8 + t2;
        uint32_t lo0, lo1;
        uint32_t hi0 = hi_lo_pack(o[nf][0] * inv0, o[nf][1] * inv0, lo0);
        uint32_t hi1 = hi_lo_pack(o[nf][2] * inv1, o[nf][3] * inv1, lo1);
        *reinterpret_cast<uint32_t*>(&atth[ob + (size_t)g * D_MODEL + c]) = hi0;
        *reinterpret_cast<uint32_t*>(&attl[ob + (size_t)g * D_MODEL + c]) = lo0;
        *reinterpret_cast<uint32_t*>(&atth[ob + (size_t)(g + 8) * D_MODEL + c]) = hi1;
        *reinterpret_cast<uint32_t*>(&attl[ob + (size_t)(g + 8) * D_MODEL + c]) = lo1;
    }
}

// ---------------------------------------------------------------------------
extern "C" void kernel_launch(void* const* d_in, const int* in_sizes, int n_in,
                              void* d_out, int out_size)
{
    const float* x    = (const float*)d_in[0];
    const float* wq   = (const float*)d_in[1];
    const float* wk   = (const float*)d_in[2];
    const float* wv   = (const float*)d_in[3];
    const float* wo_w = (const float*)d_in[4];
    const float* wo_b = (const float*)d_in[5];
    float* out = (float*)d_out;

    __nv_bfloat16 *xh, *xl, *wh, *wl, *woh, *wol, *atth, *attl;
    __half *qkvh, *qkvl;
    cudaGetSymbolAddress((void**)&xh,   g_xh);
    cudaGetSymbolAddress((void**)&xl,   g_xl);
    cudaGetSymbolAddress((void**)&wh,   g_wh);
    cudaGetSymbolAddress((void**)&wl,   g_wl);
    cudaGetSymbolAddress((void**)&woh,  g_woh);
    cudaGetSymbolAddress((void**)&wol,  g_wol);
    cudaGetSymbolAddress((void**)&qkvh, g_qkvh);
    cudaGetSymbolAddress((void**)&qkvl, g_qkvl);
    cudaGetSymbolAddress((void**)&atth, g_atth);
    cudaGetSymbolAddress((void**)&attl, g_attl);

    static bool attr_done = false;
    if (!attr_done) {
        cudaFuncSetAttribute((const void*)mma_gemm<false, true, true>,
                             cudaFuncAttributeMaxDynamicSharedMemorySize,
                             GEMM_SMEM_BYTES);
        cudaFuncSetAttribute((const void*)mma_gemm<true, false, false>,
                             cudaFuncAttributeMaxDynamicSharedMemorySize,
                             GEMM_SMEM_BYTES);
        cudaFuncSetAttribute((const void*)flash_mma,
                             cudaFuncAttributeMaxDynamicSharedMemorySize,
                             FLASH_SMEM_BYTES);
        attr_done = true;
    }

    const int total4 = XF4 + 4 * WF4;
    cvt_all<<<(total4 + 255) / 256, 256>>>(x, wq, wk, wv, wo_w,
                                           xh, xl, wh, wl, woh, wol);

    // Fused QKV projection -> fp16 hi/lo (Q pre-scaled x0.125)
    const dim3 qkv_grid(24, M_ROWS / 128);
    mma_gemm<false, true, true><<<qkv_grid, 256, GEMM_SMEM_BYTES>>>(
        xh, xl, wh, wl, nullptr, nullptr, qkvh, qkvl, D_MODEL, QKV_LD);

    // fp16 tensor-core causal flash attention -> attn bf16 hi/lo
    const dim3 flash_grid(S_LEN / 128, NHEAD, B_SZ);
    flash_mma<<<flash_grid, 256, FLASH_SMEM_BYTES>>>(qkvh, qkvl, atth, attl);

    // Output projection (bf16x3, f32 out, bias)
    const dim3 o_grid(8, M_ROWS / 128);
    mma_gemm<true, false, false><<<o_grid, 256, GEMM_SMEM_BYTES>>>(
        atth, attl, woh, wol, wo_b, out, nullptr, nullptr, D_MODEL, D_MODEL);
}

// round 14
// speedup vs baseline: 1.4488x; 1.2303x over previous
#include <cuda_runtime.h>
#include <cuda_bf16.h>
#include <cuda_fp16.h>
#include <cstdint>

#define B_SZ    2
#define S_LEN   2048
#define D_MODEL 1024
#define NHEAD   16
#define HD      64
#define M_ROWS  (B_SZ * S_LEN)      // 4096
#define QKV_LD  (3 * D_MODEL)       // 3072
#define DSQ     (D_MODEL * D_MODEL) // 1048576

// scratch (device globals) — all fp16 now
__device__ __half g_xh [(size_t)M_ROWS * D_MODEL];
__device__ __half g_xl [(size_t)M_ROWS * D_MODEL];
__device__ __half g_w  [(size_t)3 * DSQ];                 // wq|wk|wv (single fp16)
__device__ __half g_wo [(size_t)DSQ];                     // wo (single fp16)
__device__ __half g_qkvh[(size_t)M_ROWS * QKV_LD];        // Q(x0.125)|K|V  hi
__device__ __half g_qkvl[(size_t)M_ROWS * QKV_LD];        // lo (only Q used)
__device__ __half g_atth[(size_t)M_ROWS * D_MODEL];
__device__ __half g_attl[(size_t)M_ROWS * D_MODEL];

__device__ __forceinline__ uint32_t smem_u32(const void* p) {
    uint32_t a;
    asm("{ .reg .u64 t; cvta.to.shared.u64 t, %1; cvt.u32.u64 %0, t; }"
        : "=r"(a) : "l"(p));
    return a;
}

#define LDM4(r, addr) \
    asm volatile("ldmatrix.sync.aligned.m8n8.x4.shared.b16 {%0,%1,%2,%3}, [%4];" \
        : "=r"((r)[0]), "=r"((r)[1]), "=r"((r)[2]), "=r"((r)[3]) : "r"(addr))

#define LDM4T(r, addr) \
    asm volatile("ldmatrix.sync.aligned.m8n8.x4.trans.shared.b16 {%0,%1,%2,%3}, [%4];" \
        : "=r"((r)[0]), "=r"((r)[1]), "=r"((r)[2]), "=r"((r)[3]) : "r"(addr))

#define MMA_F16(d, a, b0, b1) \
    asm volatile("mma.sync.aligned.m16n8k16.row.col.f32.f16.f16.f32 " \
        "{%0,%1,%2,%3}, {%4,%5,%6,%7}, {%8,%9}, {%0,%1,%2,%3};" \
        : "+f"((d)[0]), "+f"((d)[1]), "+f"((d)[2]), "+f"((d)[3]) \
        : "r"((a)[0]), "r"((a)[1]), "r"((a)[2]), "r"((a)[3]), "r"(b0), "r"(b1))

#define CP16(dst, src) \
    asm volatile("cp.async.cg.shared.global [%0], [%1], 16;" \
        :: "r"(dst), "l"(src) : "memory")
#define CP_COMMIT() asm volatile("cp.async.commit_group;" ::: "memory")
#define CP_WAIT2()  asm volatile("cp.async.wait_group 2;" ::: "memory")

__device__ __forceinline__ uint32_t pack2h(__half a, __half b) {
    return (uint32_t)__half_as_ushort(a) |
           ((uint32_t)__half_as_ushort(b) << 16);
}

__device__ __forceinline__ uint32_t hi_lo_pack_f16(float a, float b, uint32_t& lo) {
    __half ha = __float2half_rn(a);
    __half hb = __float2half_rn(b);
    lo = pack2h(__float2half_rn(a - __half2float(ha)),
                __float2half_rn(b - __half2float(hb)));
    return pack2h(ha, hb);
}

// ---------------------------------------------------------------------------
// Fused one-shot conversions: x -> fp16 hi/lo ; weights -> single fp16
// ---------------------------------------------------------------------------
#define XF4 (M_ROWS * D_MODEL / 4)
#define WF4 (DSQ / 4)

__global__ void cvt_all(
    const float* __restrict__ x,  const float* __restrict__ wq,
    const float* __restrict__ wk, const float* __restrict__ wv,
    const float* __restrict__ wo,
    __half* __restrict__ xh, __half* __restrict__ xl,
    __half* __restrict__ w,  __half* __restrict__ wod)
{
    const int i = blockIdx.x * blockDim.x + threadIdx.x;
    if (i < XF4) {
        float4 v = reinterpret_cast<const float4*>(x)[i];
        uint32_t l0, l1;
        uint32_t h0 = hi_lo_pack_f16(v.x, v.y, l0);
        uint32_t h1 = hi_lo_pack_f16(v.z, v.w, l1);
        uint2 hh; hh.x = h0; hh.y = h1;
        uint2 ll; ll.x = l0; ll.y = l1;
        reinterpret_cast<uint2*>(xh)[i] = hh;
        reinterpret_cast<uint2*>(xl)[i] = ll;
        return;
    }
    const int k = i - XF4;
    const float* src; __half* dst; int j;
    if (k < WF4)          { src = wq; dst = w;           j = k; }
    else if (k < 2 * WF4) { src = wk; dst = w + DSQ;     j = k - WF4; }
    else if (k < 3 * WF4) { src = wv; dst = w + 2 * DSQ; j = k - 2 * WF4; }
    else if (k < 4 * WF4) { src = wo; dst = wod;         j = k - 3 * WF4; }
    else return;
    float4 v = reinterpret_cast<const float4*>(src)[j];
    uint2 hh;
    hh.x = pack2h(__float2half_rn(v.x), __float2half_rn(v.y));
    hh.y = pack2h(__float2half_rn(v.z), __float2half_rn(v.w));
    reinterpret_cast<uint2*>(dst)[j] = hh;
}

// ===========================================================================
// mma.sync fp16x2 GEMM: C = A @ W^T (+bias). A = fp16 hi/lo, W = single fp16.
// CTA 128x128, BK=16, 4-stage cp.async, 8 warps, warp tile 64x32, 2 CTAs/SM.
// Stage = Ah | Al | B tiles (3 x 6144 B with ROWB=48).
// ===========================================================================
#define ROWB    48
#define T_AH    0
#define T_AL    6144
#define T_B     12288
#define STAGE_B 18432
#define GEMM_SMEM_BYTES (4 * STAGE_B)  // 73728

template <bool HAS_BIAS, bool OUT_F16, bool SCALE_Q8>
__global__ void __launch_bounds__(256, 2) mma_gemm(
    const __half* __restrict__ Ah, const __half* __restrict__ Al,
    const __half* __restrict__ W,
    const float* __restrict__ bias,
    float* __restrict__ C,
    __half* __restrict__ Ch, __half* __restrict__ Cl,
    int K, int ldc)
{
    extern __shared__ __align__(128) char smem[];
    const uint32_t sbase = smem_u32(smem);
    const int tid  = threadIdx.x;
    const int lane = tid & 31;
    const int bx   = blockIdx.x;
    const int bm   = blockIdx.y * 128;
    const int bn   = (bx & 7) * 128;
    const int cn   = (bx >> 3) * D_MODEL + bn;
    const size_t woff = (size_t)(bx >> 3) * DSQ;

    const int wm = (tid >> 7) * 64;
    const int wn = ((tid >> 5) & 3) * 32;

    const uint32_t a_off = (uint32_t)(wm + (lane & 15)) * ROWB + (lane >> 4) * 16;
    const uint32_t b_off = (uint32_t)(wn + (lane >> 4) * 8 + (lane & 7)) * ROWB
                           + ((lane >> 3) & 1) * 16;

    const int lr = tid >> 1;
    const int lg = (tid & 1) * 8;
    const __half* pAh = Ah + (size_t)(bm + lr) * K + lg;
    const __half* pAl = Al + (size_t)(bm + lr) * K + lg;
    const __half* pW  = W + woff + (size_t)(bn + lr) * K + lg;
    const uint32_t soff = (uint32_t)lr * ROWB + (tid & 1) * 16;

    float acc[4][4][4];
#pragma unroll
    for (int i = 0; i < 4; i++)
#pragma unroll
        for (int j = 0; j < 4; j++)
#pragma unroll
            for (int r = 0; r < 4; r++) acc[i][j][r] = 0.f;

    const int nch = K / 16;

#pragma unroll
    for (int c = 0; c < 3; c++) {
        const uint32_t sb = sbase + c * STAGE_B;
        const int k0 = c * 16;
        CP16(sb + T_AH + soff, pAh + k0);
        CP16(sb + T_AL + soff, pAl + k0);
        CP16(sb + T_B  + soff, pW  + k0);
        CP_COMMIT();
    }

    for (int c = 0; c < nch; c++) {
        CP_WAIT2();
        __syncthreads();

        if (c + 3 < nch) {
            const uint32_t sb = sbase + ((c + 3) & 3) * STAGE_B;
            const int k0 = (c + 3) * 16;
            CP16(sb + T_AH + soff, pAh + k0);
            CP16(sb + T_AL + soff, pAl + k0);
            CP16(sb + T_B  + soff, pW  + k0);
        }
        CP_COMMIT();

        const uint32_t stb = sbase + (c & 3) * STAGE_B;
        uint32_t ah[4][4], al[4][4];
#pragma unroll
        for (int mf = 0; mf < 4; mf++) {
            LDM4(ah[mf], stb + T_AH + a_off + mf * (16 * ROWB));
            LDM4(al[mf], stb + T_AL + a_off + mf * (16 * ROWB));
        }
        uint32_t bh[2][4];
#pragma unroll
        for (int p = 0; p < 2; p++)
            LDM4(bh[p], stb + T_B + b_off + p * (16 * ROWB));

#pragma unroll
        for (int mf = 0; mf < 4; mf++) {
#pragma unroll
            for (int nf = 0; nf < 4; nf++) {
                const uint32_t b0 = bh[nf >> 1][(nf & 1) * 2];
                const uint32_t b1 = bh[nf >> 1][(nf & 1) * 2 + 1];
                MMA_F16(acc[mf][nf], ah[mf], b0, b1);
                MMA_F16(acc[mf][nf], al[mf], b0, b1);
            }
        }
    }

    const int g  = lane >> 2;
    const int t2 = (lane & 3) * 2;
    const float sc = (SCALE_Q8 && bx < 8) ? 0.125f : 1.0f;
#pragma unroll
    for (int mf = 0; mf < 4; mf++) {
#pragma unroll
        for (int nf = 0; nf < 4; nf++) {
            const int m = bm + wm + mf * 16 + g;
            const int n = cn + wn + nf * 8 + t2;
            float2 v0, v1;
            v0.x = acc[mf][nf][0]; v0.y = acc[mf][nf][1];
            v1.x = acc[mf][nf][2]; v1.y = acc[mf][nf][3];
            if (OUT_F16) {
                v0.x *= sc; v0.y *= sc; v1.x *= sc; v1.y *= sc;
                uint32_t l0_, l1_;
                uint32_t h0_ = hi_lo_pack_f16(v0.x, v0.y, l0_);
                uint32_t h1_ = hi_lo_pack_f16(v1.x, v1.y, l1_);
                *reinterpret_cast<uint32_t*>(&Ch[(size_t)m * ldc + n]) = h0_;
                *reinterpret_cast<uint32_t*>(&Cl[(size_t)m * ldc + n]) = l0_;
                *reinterpret_cast<uint32_t*>(&Ch[(size_t)(m + 8) * ldc + n]) = h1_;
                *reinterpret_cast<uint32_t*>(&Cl[(size_t)(m + 8) * ldc + n]) = l1_;
            } else {
                if (HAS_BIAS) {
                    const float2 bv = *reinterpret_cast<const float2*>(&bias[n]);
                    v0.x += bv.x; v0.y += bv.y;
                    v1.x += bv.x; v1.y += bv.y;
                }
                *reinterpret_cast<float2*>(&C[(size_t)m * ldc + n]) = v0;
                *reinterpret_cast<float2*>(&C[(size_t)(m + 8) * ldc + n]) = v1;
            }
        }
    }
}

// ===========================================================================
// fp16 tensor-core causal flash attention (R13-verified), 4-stage KV ring.
// Q: fp16 hi/lo (regs). K,V: single fp16. P: fp16 hi/lo (regs).
// Epilogue writes attn as fp16 hi/lo for the fp16x2 O-projection.
// ===========================================================================
#define FROWB 144
#define KV_K  0
#define KV_V  9216
#define KV_STAGE 18432
#define SQH   0
#define SQL   18432
#define FLASH_SMEM_BYTES (4 * KV_STAGE)   // 73728

__global__ void __launch_bounds__(256) flash_mma(
    const __half* __restrict__ qkvh,
    const __half* __restrict__ qkvl,
    __half* __restrict__ atth,
    __half* __restrict__ attl)
{
    extern __shared__ __align__(128) char smem[];
    const uint32_t sbase = smem_u32(smem);
    const int tid  = threadIdx.x;
    const int lane = tid & 31;
    const int w    = tid >> 5;
    const int qt   = (gridDim.x - 1) - blockIdx.x;
    const int h    = blockIdx.y;
    const int b    = blockIdx.z;

    const size_t head_base = (size_t)b * S_LEN * QKV_LD + (size_t)h * HD;

    {
        const int r = tid >> 1;
        const int g0 = (tid & 1) * 4;
        const __half* qrh = qkvh + head_base + (size_t)(qt * 128 + r) * QKV_LD;
        const __half* qrl = qkvl + head_base + (size_t)(qt * 128 + r) * QKV_LD;
#pragma unroll
        for (int t = 0; t < 4; t++) {
            const int gg = g0 + t;
            const uint32_t off = (uint32_t)r * FROWB + gg * 16;
            *reinterpret_cast<uint4*>(smem + SQH + off) =
                *reinterpret_cast<const uint4*>(qrh + gg * 8);
            *reinterpret_cast<uint4*>(smem + SQL + off) =
                *reinterpret_cast<const uint4*>(qrl + gg * 8);
        }
    }
    __syncthreads();

    uint32_t qh[4][4], ql[4][4];
    {
        const uint32_t a_off = (uint32_t)(w * 16 + (lane & 15)) * FROWB
                               + ((lane >> 4) * 8) * 2;
#pragma unroll
        for (int ks = 0; ks < 4; ks++) {
            LDM4(qh[ks], sbase + SQH + a_off + ks * 32);
            LDM4(ql[ks], sbase + SQL + a_off + ks * 32);
        }
    }
    __syncthreads();

    float o[8][4];
#pragma unroll
    for (int nf = 0; nf < 8; nf++)
#pragma unroll
        for (int r = 0; r < 4; r++) o[nf][r] = 0.f;
    float m0 = -1e30f, m1 = -1e30f, l0 = 0.f, l1 = 0.f;

    const int g  = lane >> 2;
    const int t2 = (lane & 3) * 2;
    const int wrow = qt * 128 + w * 16;
    const int row0 = wrow + g;
    const int row1 = row0 + 8;

    const uint32_t kb_off = (uint32_t)((lane >> 4) * 8 + (lane & 7)) * FROWB
                            + (((lane >> 3) & 1) * 8) * 2;
    const uint32_t vt_row = (uint32_t)(lane & 15) * FROWB + ((lane >> 4) * 8) * 2;

    const int klr = tid >> 2;
    const int kg0 = (tid & 3) * 2;

    const int kt_end = 2 * qt + 1;

#pragma unroll
    for (int c = 0; c < 3; c++) {
        const uint32_t sb = sbase + c * KV_STAGE;
        const size_t rowb = head_base + (size_t)(c * 64 + klr) * QKV_LD;
#pragma unroll
        for (int t = 0; t < 2; t++) {
            const int gg = kg0 + t;
            const uint32_t off = (uint32_t)klr * FROWB + gg * 16;
            CP16(sb + KV_K + off, qkvh + rowb + D_MODEL + gg * 8);
            CP16(sb + KV_V + off, qkvh + rowb + 2 * D_MODEL + gg * 8);
        }
        CP_COMMIT();
    }

    for (int kt = 0; kt <= kt_end; kt++) {
        CP_WAIT2();
        __syncthreads();

        if (kt + 3 <= kt_end) {
            const uint32_t sb = sbase + ((kt + 3) & 3) * KV_STAGE;
            const size_t rowb = head_base + (size_t)((kt + 3) * 64 + klr) * QKV_LD;
#pragma unroll
            for (int t = 0; t < 2; t++) {
                const int gg = kg0 + t;
                const uint32_t off = (uint32_t)klr * FROWB + gg * 16;
                CP16(sb + KV_K + off, qkvh + rowb + D_MODEL + gg * 8);
                CP16(sb + KV_V + off, qkvh + rowb + 2 * D_MODEL + gg * 8);
            }
        }
        CP_COMMIT();

        const bool active = (kt * 64 <= wrow + 15);
        if (active) {
            const uint32_t stb = sbase + (kt & 3) * KV_STAGE;
            float s[8][4];
#pragma unroll
            for (int nf = 0; nf < 8; nf++)
#pragma unroll
                for (int r = 0; r < 4; r++) s[nf][r] = 0.f;

#pragma unroll
            for (int ks = 0; ks < 4; ks++) {
#pragma unroll
                for (int p = 0; p < 4; p++) {
                    uint32_t kh[4];
                    LDM4(kh, stb + KV_K + kb_off + p * (16 * FROWB) + ks * 32);
                    MMA_F16(s[2 * p],     qh[ks], kh[0], kh[1]);
                    MMA_F16(s[2 * p + 1], qh[ks], kh[2], kh[3]);
                    MMA_F16(s[2 * p],     ql[ks], kh[0], kh[1]);
                    MMA_F16(s[2 * p + 1], ql[ks], kh[2], kh[3]);
                }
            }

            if (kt * 64 + 63 > wrow) {
#pragma unroll
                for (int nf = 0; nf < 8; nf++) {
                    const int c0 = kt * 64 + nf * 8 + t2;
                    if (c0     > row0) s[nf][0] = -1e30f;
                    if (c0 + 1 > row0) s[nf][1] = -1e30f;
                    if (c0     > row1) s[nf][2] = -1e30f;
                    if (c0 + 1 > row1) s[nf][3] = -1e30f;
                }
            }

            float mx0 = s[0][0], mx1 = s[0][2];
#pragma unroll
            for (int nf = 0; nf < 8; nf++) {
                mx0 = fmaxf(mx0, fmaxf(s[nf][0], s[nf][1]));
                mx1 = fmaxf(mx1, fmaxf(s[nf][2], s[nf][3]));
            }
            mx0 = fmaxf(mx0, __shfl_xor_sync(0xffffffffu, mx0, 1));
            mx0 = fmaxf(mx0, __shfl_xor_sync(0xffffffffu, mx0, 2));
            mx1 = fmaxf(mx1, __shfl_xor_sync(0xffffffffu, mx1, 1));
            mx1 = fmaxf(mx1, __shfl_xor_sync(0xffffffffu, mx1, 2));

            const float nm0 = fmaxf(m0, mx0), nm1 = fmaxf(m1, mx1);
            const float a0 = __expf(m0 - nm0), a1 = __expf(m1 - nm1);
            m0 = nm0; m1 = nm1;

            float sum0 = 0.f, sum1 = 0.f;
#pragma unroll
            for (int nf = 0; nf < 8; nf++) {
                s[nf][0] = __expf(s[nf][0] - nm0);
                s[nf][1] = __expf(s[nf][1] - nm0);
                s[nf][2] = __expf(s[nf][2] - nm1);
                s[nf][3] = __expf(s[nf][3] - nm1);
                sum0 += s[nf][0] + s[nf][1];
                sum1 += s[nf][2] + s[nf][3];
            }
            sum0 += __shfl_xor_sync(0xffffffffu, sum0, 1);
            sum0 += __shfl_xor_sync(0xffffffffu, sum0, 2);
            sum1 += __shfl_xor_sync(0xffffffffu, sum1, 1);
            sum1 += __shfl_xor_sync(0xffffffffu, sum1, 2);
            l0 = l0 * a0 + sum0;
            l1 = l1 * a1 + sum1;

#pragma unroll
            for (int nf = 0; nf < 8; nf++) {
                o[nf][0] *= a0; o[nf][1] *= a0;
                o[nf][2] *= a1; o[nf][3] *= a1;
            }

#pragma unroll
            for (int j = 0; j < 4; j++) {
                uint32_t ph[4], pl[4];
                ph[0] = hi_lo_pack_f16(s[2 * j][0],     s[2 * j][1],     pl[0]);
                ph[1] = hi_lo_pack_f16(s[2 * j][2],     s[2 * j][3],     pl[1]);
                ph[2] = hi_lo_pack_f16(s[2 * j + 1][0], s[2 * j + 1][1], pl[2]);
                ph[3] = hi_lo_pack_f16(s[2 * j + 1][2], s[2 * j + 1][3], pl[3]);

                const uint32_t vbase = (uint32_t)(j * 16) * FROWB + vt_row;
#pragma unroll
                for (int hg = 0; hg < 4; hg++) {
                    uint32_t vh[4];
                    LDM4T(vh, stb + KV_V + vbase + hg * 32);
                    MMA_F16(o[2 * hg],     ph, vh[0], vh[1]);
                    MMA_F16(o[2 * hg + 1], ph, vh[2], vh[3]);
                    MMA_F16(o[2 * hg],     pl, vh[0], vh[1]);
                    MMA_F16(o[2 * hg + 1], pl, vh[2], vh[3]);
                }
            }
        }
    }

    // ---- Normalize and write attn as fp16 hi/lo ----
    const float inv0 = 1.f / l0, inv1 = 1.f / l1;
    const size_t ob = ((size_t)b * S_LEN + qt * 128 + w * 16) * D_MODEL
                      + (size_t)h * HD;
#pragma unroll
    for (int nf = 0; nf < 8; nf++) {
        const int c = nf * 8 + t2;
        uint32_t lo0, lo1;
        uint32_t hi0 = hi_lo_pack_f16(o[nf][0] * inv0, o[nf][1] * inv0, lo0);
        uint32_t hi1 = hi_lo_pack_f16(o[nf][2] * inv1, o[nf][3] * inv1, lo1);
        *reinterpret_cast<uint32_t*>(&atth[ob + (size_t)g * D_MODEL + c]) = hi0;
        *reinterpret_cast<uint32_t*>(&attl[ob + (size_t)g * D_MODEL + c]) = lo0;
        *reinterpret_cast<uint32_t*>(&atth[ob + (size_t)(g + 8) * D_MODEL + c]) = hi1;
        *reinterpret_cast<uint32_t*>(&attl[ob + (size_t)(g + 8) * D_MODEL + c]) = lo1;
    }
}

// ---------------------------------------------------------------------------
extern "C" void kernel_launch(void* const* d_in, const int* in_sizes, int n_in,
                              void* d_out, int out_size)
{
    const float* x    = (const float*)d_in[0];
    const float* wq   = (const float*)d_in[1];
    const float* wk   = (const float*)d_in[2];
    const float* wv   = (const float*)d_in[3];
    const float* wo_w = (const float*)d_in[4];
    const float* wo_b = (const float*)d_in[5];
    float* out = (float*)d_out;

    __half *xh, *xl, *w, *wo, *qkvh, *qkvl, *atth, *attl;
    cudaGetSymbolAddress((void**)&xh,   g_xh);
    cudaGetSymbolAddress((void**)&xl,   g_xl);
    cudaGetSymbolAddress((void**)&w,    g_w);
    cudaGetSymbolAddress((void**)&wo,   g_wo);
    cudaGetSymbolAddress((void**)&qkvh, g_qkvh);
    cudaGetSymbolAddress((void**)&qkvl, g_qkvl);
    cudaGetSymbolAddress((void**)&atth, g_atth);
    cudaGetSymbolAddress((void**)&attl, g_attl);

    static bool attr_done = false;
    if (!attr_done) {
        cudaFuncSetAttribute((const void*)mma_gemm<false, true, true>,
                             cudaFuncAttributeMaxDynamicSharedMemorySize,
                             GEMM_SMEM_BYTES);
        cudaFuncSetAttribute((const void*)mma_gemm<true, false, false>,
                             cudaFuncAttributeMaxDynamicSharedMemorySize,
                             GEMM_SMEM_BYTES);
        cudaFuncSetAttribute((const void*)flash_mma,
                             cudaFuncAttributeMaxDynamicSharedMemorySize,
                             FLASH_SMEM_BYTES);
        attr_done = true;
    }

    const int total4 = XF4 + 4 * WF4;
    cvt_all<<<(total4 + 255) / 256, 256>>>(x, wq, wk, wv, wo_w, xh, xl, w, wo);

    // Fused QKV projection -> fp16 hi/lo (Q pre-scaled x0.125)
    const dim3 qkv_grid(24, M_ROWS / 128);
    mma_gemm<false, true, true><<<qkv_grid, 256, GEMM_SMEM_BYTES>>>(
        xh, xl, w, nullptr, nullptr, qkvh, qkvl, D_MODEL, QKV_LD);

    // fp16 tensor-core causal flash attention -> attn fp16 hi/lo
    const dim3 flash_grid(S_LEN / 128, NHEAD, B_SZ);
    flash_mma<<<flash_grid, 256, FLASH_SMEM_BYTES>>>(qkvh, qkvl, atth, attl);

    // Output projection (fp16x2, f32 out, bias)
    const dim3 o_grid(8, M_ROWS / 128);
    mma_gemm<true, false, false><<<o_grid, 256, GEMM_SMEM_BYTES>>>(
        atth, attl, wo, wo_b, out, nullptr, nullptr, D_MODEL, D_MODEL);
}

// round 15
// speedup vs baseline: 1.6145x; 1.1144x over previous
#include <cuda_runtime.h>
#include <cuda_fp16.h>
#include <cstdint>

#define B_SZ    2
#define S_LEN   2048
#define D_MODEL 1024
#define NHEAD   16
#define HD      64
#define M_ROWS  (B_SZ * S_LEN)      // 4096
#define QKV_LD  (3 * D_MODEL)       // 3072
#define DSQ     (D_MODEL * D_MODEL) // 1048576

// scratch (device globals)
__device__ __half g_xh [(size_t)M_ROWS * D_MODEL];
__device__ __half g_xl [(size_t)M_ROWS * D_MODEL];
__device__ __half g_w  [(size_t)3 * DSQ];                 // wq|wk|wv (single fp16)
__device__ __half g_wo [(size_t)DSQ];                     // wo (single fp16)
__device__ __half g_qkv[(size_t)M_ROWS * QKV_LD];         // Q(x0.125)|K|V (single fp16)
__device__ __half g_atth[(size_t)M_ROWS * D_MODEL];
__device__ __half g_attl[(size_t)M_ROWS * D_MODEL];

__device__ __forceinline__ uint32_t smem_u32(const void* p) {
    uint32_t a;
    asm("{ .reg .u64 t; cvta.to.shared.u64 t, %1; cvt.u32.u64 %0, t; }"
        : "=r"(a) : "l"(p));
    return a;
}

#define LDM4(r, addr) \
    asm volatile("ldmatrix.sync.aligned.m8n8.x4.shared.b16 {%0,%1,%2,%3}, [%4];" \
        : "=r"((r)[0]), "=r"((r)[1]), "=r"((r)[2]), "=r"((r)[3]) : "r"(addr))

#define LDM4T(r, addr) \
    asm volatile("ldmatrix.sync.aligned.m8n8.x4.trans.shared.b16 {%0,%1,%2,%3}, [%4];" \
        : "=r"((r)[0]), "=r"((r)[1]), "=r"((r)[2]), "=r"((r)[3]) : "r"(addr))

#define MMA_F16(d, a, b0, b1) \
    asm volatile("mma.sync.aligned.m16n8k16.row.col.f32.f16.f16.f32 " \
        "{%0,%1,%2,%3}, {%4,%5,%6,%7}, {%8,%9}, {%0,%1,%2,%3};" \
        : "+f"((d)[0]), "+f"((d)[1]), "+f"((d)[2]), "+f"((d)[3]) \
        : "r"((a)[0]), "r"((a)[1]), "r"((a)[2]), "r"((a)[3]), "r"(b0), "r"(b1))

#define CP16(dst, src) \
    asm volatile("cp.async.cg.shared.global [%0], [%1], 16;" \
        :: "r"(dst), "l"(src) : "memory")
#define CP_COMMIT() asm volatile("cp.async.commit_group;" ::: "memory")
#define CP_WAIT2()  asm volatile("cp.async.wait_group 2;" ::: "memory")

__device__ __forceinline__ uint32_t pack2h(__half a, __half b) {
    return (uint32_t)__half_as_ushort(a) |
           ((uint32_t)__half_as_ushort(b) << 16);
}

__device__ __forceinline__ uint32_t hi_lo_pack_f16(float a, float b, uint32_t& lo) {
    __half ha = __float2half_rn(a);
    __half hb = __float2half_rn(b);
    lo = pack2h(__float2half_rn(a - __half2float(ha)),
                __float2half_rn(b - __half2float(hb)));
    return pack2h(ha, hb);
}

// ---------------------------------------------------------------------------
// Fused one-shot conversions: x -> fp16 hi/lo ; weights -> single fp16
// ---------------------------------------------------------------------------
#define XF4 (M_ROWS * D_MODEL / 4)
#define WF4 (DSQ / 4)

__global__ void cvt_all(
    const float* __restrict__ x,  const float* __restrict__ wq,
    const float* __restrict__ wk, const float* __restrict__ wv,
    const float* __restrict__ wo,
    __half* __restrict__ xh, __half* __restrict__ xl,
    __half* __restrict__ w,  __half* __restrict__ wod)
{
    const int i = blockIdx.x * blockDim.x + threadIdx.x;
    if (i < XF4) {
        float4 v = reinterpret_cast<const float4*>(x)[i];
        uint32_t l0, l1;
        uint32_t h0 = hi_lo_pack_f16(v.x, v.y, l0);
        uint32_t h1 = hi_lo_pack_f16(v.z, v.w, l1);
        uint2 hh; hh.x = h0; hh.y = h1;
        uint2 ll; ll.x = l0; ll.y = l1;
        reinterpret_cast<uint2*>(xh)[i] = hh;
        reinterpret_cast<uint2*>(xl)[i] = ll;
        return;
    }
    const int k = i - XF4;
    const float* src; __half* dst; int j;
    if (k < WF4)          { src = wq; dst = w;           j = k; }
    else if (k < 2 * WF4) { src = wk; dst = w + DSQ;     j = k - WF4; }
    else if (k < 3 * WF4) { src = wv; dst = w + 2 * DSQ; j = k - 2 * WF4; }
    else if (k < 4 * WF4) { src = wo; dst = wod;         j = k - 3 * WF4; }
    else return;
    float4 v = reinterpret_cast<const float4*>(src)[j];
    uint2 hh;
    hh.x = pack2h(__float2half_rn(v.x), __float2half_rn(v.y));
    hh.y = pack2h(__float2half_rn(v.z), __float2half_rn(v.w));
    reinterpret_cast<uint2*>(dst)[j] = hh;
}

// ===========================================================================
// mma.sync fp16x2 GEMM: C = A @ W^T (+bias). A = fp16 hi/lo, W = single fp16.
// OUT_F16: write single fp16 (+Q scale). CTA 128x128, BK=16, 4-stage cp.async.
// ===========================================================================
#define ROWB    48
#define T_AH    0
#define T_AL    6144
#define T_B     12288
#define STAGE_B 18432
#define GEMM_SMEM_BYTES (4 * STAGE_B)  // 73728

template <bool HAS_BIAS, bool OUT_F16, bool SCALE_Q8>
__global__ void __launch_bounds__(256, 2) mma_gemm(
    const __half* __restrict__ Ah, const __half* __restrict__ Al,
    const __half* __restrict__ W,
    const float* __restrict__ bias,
    float* __restrict__ C,
    __half* __restrict__ Ch,
    int K, int ldc)
{
    extern __shared__ __align__(128) char smem[];
    const uint32_t sbase = smem_u32(smem);
    const int tid  = threadIdx.x;
    const int lane = tid & 31;
    const int bx   = blockIdx.x;
    const int bm   = blockIdx.y * 128;
    const int bn   = (bx & 7) * 128;
    const int cn   = (bx >> 3) * D_MODEL + bn;
    const size_t woff = (size_t)(bx >> 3) * DSQ;

    const int wm = (tid >> 7) * 64;
    const int wn = ((tid >> 5) & 3) * 32;

    const uint32_t a_off = (uint32_t)(wm + (lane & 15)) * ROWB + (lane >> 4) * 16;
    const uint32_t b_off = (uint32_t)(wn + (lane >> 4) * 8 + (lane & 7)) * ROWB
                           + ((lane >> 3) & 1) * 16;

    const int lr = tid >> 1;
    const int lg = (tid & 1) * 8;
    const __half* pAh = Ah + (size_t)(bm + lr) * K + lg;
    const __half* pAl = Al + (size_t)(bm + lr) * K + lg;
    const __half* pW  = W + woff + (size_t)(bn + lr) * K + lg;
    const uint32_t soff = (uint32_t)lr * ROWB + (tid & 1) * 16;

    float acc[4][4][4];
#pragma unroll
    for (int i = 0; i < 4; i++)
#pragma unroll
        for (int j = 0; j < 4; j++)
#pragma unroll
            for (int r = 0; r < 4; r++) acc[i][j][r] = 0.f;

    const int nch = K / 16;

#pragma unroll
    for (int c = 0; c < 3; c++) {
        const uint32_t sb = sbase + c * STAGE_B;
        const int k0 = c * 16;
        CP16(sb + T_AH + soff, pAh + k0);
        CP16(sb + T_AL + soff, pAl + k0);
        CP16(sb + T_B  + soff, pW  + k0);
        CP_COMMIT();
    }

    for (int c = 0; c < nch; c++) {
        CP_WAIT2();
        __syncthreads();

        if (c + 3 < nch) {
            const uint32_t sb = sbase + ((c + 3) & 3) * STAGE_B;
            const int k0 = (c + 3) * 16;
            CP16(sb + T_AH + soff, pAh + k0);
            CP16(sb + T_AL + soff, pAl + k0);
            CP16(sb + T_B  + soff, pW  + k0);
        }
        CP_COMMIT();

        const uint32_t stb = sbase + (c & 3) * STAGE_B;
        uint32_t ah[4][4], al[4][4];
#pragma unroll
        for (int mf = 0; mf < 4; mf++) {
            LDM4(ah[mf], stb + T_AH + a_off + mf * (16 * ROWB));
            LDM4(al[mf], stb + T_AL + a_off + mf * (16 * ROWB));
        }
        uint32_t bh[2][4];
#pragma unroll
        for (int p = 0; p < 2; p++)
            LDM4(bh[p], stb + T_B + b_off + p * (16 * ROWB));

#pragma unroll
        for (int mf = 0; mf < 4; mf++) {
#pragma unroll
            for (int nf = 0; nf < 4; nf++) {
                const uint32_t b0 = bh[nf >> 1][(nf & 1) * 2];
                const uint32_t b1 = bh[nf >> 1][(nf & 1) * 2 + 1];
                MMA_F16(acc[mf][nf], ah[mf], b0, b1);
                MMA_F16(acc[mf][nf], al[mf], b0, b1);
            }
        }
    }

    const int g  = lane >> 2;
    const int t2 = (lane & 3) * 2;
    const float sc = (SCALE_Q8 && bx < 8) ? 0.125f : 1.0f;
#pragma unroll
    for (int mf = 0; mf < 4; mf++) {
#pragma unroll
        for (int nf = 0; nf < 4; nf++) {
            const int m = bm + wm + mf * 16 + g;
            const int n = cn + wn + nf * 8 + t2;
            float2 v0, v1;
            v0.x = acc[mf][nf][0]; v0.y = acc[mf][nf][1];
            v1.x = acc[mf][nf][2]; v1.y = acc[mf][nf][3];
            if (OUT_F16) {
                v0.x *= sc; v0.y *= sc; v1.x *= sc; v1.y *= sc;
                *reinterpret_cast<uint32_t*>(&Ch[(size_t)m * ldc + n]) =
                    pack2h(__float2half_rn(v0.x), __float2half_rn(v0.y));
                *reinterpret_cast<uint32_t*>(&Ch[(size_t)(m + 8) * ldc + n]) =
                    pack2h(__float2half_rn(v1.x), __float2half_rn(v1.y));
            } else {
                if (HAS_BIAS) {
                    const float2 bv = *reinterpret_cast<const float2*>(&bias[n]);
                    v0.x += bv.x; v0.y += bv.y;
                    v1.x += bv.x; v1.y += bv.y;
                }
                *reinterpret_cast<float2*>(&C[(size_t)m * ldc + n]) = v0;
                *reinterpret_cast<float2*>(&C[(size_t)(m + 8) * ldc + n]) = v1;
            }
        }
    }
}

// ===========================================================================
// fp16 tensor-core causal flash attention, 4-stage KV ring, 2 CTAs/SM.
// Q, K, V: single fp16. P: fp16 hi/lo (in regs).
// QK = 1 mma/frag-pair; PV = PhV + PlV. 96 MMAs/tile.
// ===========================================================================
#define FROWB 144
#define KV_K  0
#define KV_V  9216
#define KV_STAGE 18432
#define SQH   0
#define FLASH_SMEM_BYTES (4 * KV_STAGE)   // 73728

__global__ void __launch_bounds__(256, 2) flash_mma(
    const __half* __restrict__ qkv,
    __half* __restrict__ atth,
    __half* __restrict__ attl)
{
    extern __shared__ __align__(128) char smem[];
    const uint32_t sbase = smem_u32(smem);
    const int tid  = threadIdx.x;
    const int lane = tid & 31;
    const int w    = tid >> 5;
    const int qt   = (gridDim.x - 1) - blockIdx.x;
    const int h    = blockIdx.y;
    const int b    = blockIdx.z;

    const size_t head_base = (size_t)b * S_LEN * QKV_LD + (size_t)h * HD;

    // ---- Stage Q (single fp16, pre-scaled), consume to registers ----
    {
        const int r = tid >> 1;
        const int g0 = (tid & 1) * 4;
        const __half* qr = qkv + head_base + (size_t)(qt * 128 + r) * QKV_LD;
#pragma unroll
        for (int t = 0; t < 4; t++) {
            const int gg = g0 + t;
            *reinterpret_cast<uint4*>(smem + SQH + (uint32_t)r * FROWB + gg * 16) =
                *reinterpret_cast<const uint4*>(qr + gg * 8);
        }
    }
    __syncthreads();

    uint32_t qh[4][4];
    {
        const uint32_t a_off = (uint32_t)(w * 16 + (lane & 15)) * FROWB
                               + ((lane >> 4) * 8) * 2;
#pragma unroll
        for (int ks = 0; ks < 4; ks++)
            LDM4(qh[ks], sbase + SQH + a_off + ks * 32);
    }
    __syncthreads();

    float o[8][4];
#pragma unroll
    for (int nf = 0; nf < 8; nf++)
#pragma unroll
        for (int r = 0; r < 4; r++) o[nf][r] = 0.f;
    float m0 = -1e30f, m1 = -1e30f, l0 = 0.f, l1 = 0.f;

    const int g  = lane >> 2;
    const int t2 = (lane & 3) * 2;
    const int wrow = qt * 128 + w * 16;
    const int row0 = wrow + g;
    const int row1 = row0 + 8;

    const uint32_t kb_off = (uint32_t)((lane >> 4) * 8 + (lane & 7)) * FROWB
                            + (((lane >> 3) & 1) * 8) * 2;
    const uint32_t vt_row = (uint32_t)(lane & 15) * FROWB + ((lane >> 4) * 8) * 2;

    const int klr = tid >> 2;
    const int kg0 = (tid & 3) * 2;

    const int kt_end = 2 * qt + 1;

#pragma unroll
    for (int c = 0; c < 3; c++) {
        const uint32_t sb = sbase + c * KV_STAGE;
        const size_t rowb = head_base + (size_t)(c * 64 + klr) * QKV_LD;
#pragma unroll
        for (int t = 0; t < 2; t++) {
            const int gg = kg0 + t;
            const uint32_t off = (uint32_t)klr * FROWB + gg * 16;
            CP16(sb + KV_K + off, qkv + rowb + D_MODEL + gg * 8);
            CP16(sb + KV_V + off, qkv + rowb + 2 * D_MODEL + gg * 8);
        }
        CP_COMMIT();
    }

    for (int kt = 0; kt <= kt_end; kt++) {
        CP_WAIT2();
        __syncthreads();

        if (kt + 3 <= kt_end) {
            const uint32_t sb = sbase + ((kt + 3) & 3) * KV_STAGE;
            const size_t rowb = head_base + (size_t)((kt + 3) * 64 + klr) * QKV_LD;
#pragma unroll
            for (int t = 0; t < 2; t++) {
                const int gg = kg0 + t;
                const uint32_t off = (uint32_t)klr * FROWB + gg * 16;
                CP16(sb + KV_K + off, qkv + rowb + D_MODEL + gg * 8);
                CP16(sb + KV_V + off, qkv + rowb + 2 * D_MODEL + gg * 8);
            }
        }
        CP_COMMIT();

        const bool active = (kt * 64 <= wrow + 15);
        if (active) {
            const uint32_t stb = sbase + (kt & 3) * KV_STAGE;
            float s[8][4];
#pragma unroll
            for (int nf = 0; nf < 8; nf++)
#pragma unroll
                for (int r = 0; r < 4; r++) s[nf][r] = 0.f;

#pragma unroll
            for (int ks = 0; ks < 4; ks++) {
#pragma unroll
                for (int p = 0; p < 4; p++) {
                    uint32_t kh[4];
                    LDM4(kh, stb + KV_K + kb_off + p * (16 * FROWB) + ks * 32);
                    MMA_F16(s[2 * p],     qh[ks], kh[0], kh[1]);
                    MMA_F16(s[2 * p + 1], qh[ks], kh[2], kh[3]);
                }
            }

            if (kt * 64 + 63 > wrow) {
#pragma unroll
                for (int nf = 0; nf < 8; nf++) {
                    const int c0 = kt * 64 + nf * 8 + t2;
                    if (c0     > row0) s[nf][0] = -1e30f;
                    if (c0 + 1 > row0) s[nf][1] = -1e30f;
                    if (c0     > row1) s[nf][2] = -1e30f;
                    if (c0 + 1 > row1) s[nf][3] = -1e30f;
                }
            }

            float mx0 = s[0][0], mx1 = s[0][2];
#pragma unroll
            for (int nf = 0; nf < 8; nf++) {
                mx0 = fmaxf(mx0, fmaxf(s[nf][0], s[nf][1]));
                mx1 = fmaxf(mx1, fmaxf(s[nf][2], s[nf][3]));
            }
            mx0 = fmaxf(mx0, __shfl_xor_sync(0xffffffffu, mx0, 1));
            mx0 = fmaxf(mx0, __shfl_xor_sync(0xffffffffu, mx0, 2));
            mx1 = fmaxf(mx1, __shfl_xor_sync(0xffffffffu, mx1, 1));
            mx1 = fmaxf(mx1, __shfl_xor_sync(0xffffffffu, mx1, 2));

            const float nm0 = fmaxf(m0, mx0), nm1 = fmaxf(m1, mx1);
            const float a0 = __expf(m0 - nm0), a1 = __expf(m1 - nm1);
            m0 = nm0; m1 = nm1;

            float sum0 = 0.f, sum1 = 0.f;
#pragma unroll
            for (int nf = 0; nf < 8; nf++) {
                s[nf][0] = __expf(s[nf][0] - nm0);
                s[nf][1] = __expf(s[nf][1] - nm0);
                s[nf][2] = __expf(s[nf][2] - nm1);
                s[nf][3] = __expf(s[nf][3] - nm1);
                sum0 += s[nf][0] + s[nf][1];
                sum1 += s[nf][2] + s[nf][3];
            }
            sum0 += __shfl_xor_sync(0xffffffffu, sum0, 1);
            sum0 += __shfl_xor_sync(0xffffffffu, sum0, 2);
            sum1 += __shfl_xor_sync(0xffffffffu, sum1, 1);
            sum1 += __shfl_xor_sync(0xffffffffu, sum1, 2);
            l0 = l0 * a0 + sum0;
            l1 = l1 * a1 + sum1;

#pragma unroll
            for (int nf = 0; nf < 8; nf++) {
                o[nf][0] *= a0; o[nf][1] *= a0;
                o[nf][2] *= a1; o[nf][3] *= a1;
            }

#pragma unroll
            for (int j = 0; j < 4; j++) {
                uint32_t ph[4], pl[4];
                ph[0] = hi_lo_pack_f16(s[2 * j][0],     s[2 * j][1],     pl[0]);
                ph[1] = hi_lo_pack_f16(s[2 * j][2],     s[2 * j][3],     pl[1]);
                ph[2] = hi_lo_pack_f16(s[2 * j + 1][0], s[2 * j + 1][1], pl[2]);
                ph[3] = hi_lo_pack_f16(s[2 * j + 1][2], s[2 * j + 1][3], pl[3]);

                const uint32_t vbase = (uint32_t)(j * 16) * FROWB + vt_row;
#pragma unroll
                for (int hg = 0; hg < 4; hg++) {
                    uint32_t vh[4];
                    LDM4T(vh, stb + KV_V + vbase + hg * 32);
                    MMA_F16(o[2 * hg],     ph, vh[0], vh[1]);
                    MMA_F16(o[2 * hg + 1], ph, vh[2], vh[3]);
                    MMA_F16(o[2 * hg],     pl, vh[0], vh[1]);
                    MMA_F16(o[2 * hg + 1], pl, vh[2], vh[3]);
                }
            }
        }
    }

    // ---- Normalize and write attn as fp16 hi/lo ----
    const float inv0 = 1.f / l0, inv1 = 1.f / l1;
    const size_t ob = ((size_t)b * S_LEN + qt * 128 + w * 16) * D_MODEL
                      + (size_t)h * HD;
#pragma unroll
    for (int nf = 0; nf < 8; nf++) {
        const int c = nf * 8 + t2;
        uint32_t lo0, lo1;
        uint32_t hi0 = hi_lo_pack_f16(o[nf][0] * inv0, o[nf][1] * inv0, lo0);
        uint32_t hi1 = hi_lo_pack_f16(o[nf][2] * inv1, o[nf][3] * inv1, lo1);
        *reinterpret_cast<uint32_t*>(&atth[ob + (size_t)g * D_MODEL + c]) = hi0;
        *reinterpret_cast<uint32_t*>(&attl[ob + (size_t)g * D_MODEL + c]) = lo0;
        *reinterpret_cast<uint32_t*>(&atth[ob + (size_t)(g + 8) * D_MODEL + c]) = hi1;
        *reinterpret_cast<uint32_t*>(&attl[ob + (size_t)(g + 8) * D_MODEL + c]) = lo1;
    }
}

// ---------------------------------------------------------------------------
extern "C" void kernel_launch(void* const* d_in, const int* in_sizes, int n_in,
                              void* d_out, int out_size)
{
    const float* x    = (const float*)d_in[0];
    const float* wq   = (const float*)d_in[1];
    const float* wk   = (const float*)d_in[2];
    const float* wv   = (const float*)d_in[3];
    const float* wo_w = (const float*)d_in[4];
    const float* wo_b = (const float*)d_in[5];
    float* out = (float*)d_out;

    __half *xh, *xl, *w, *wo, *qkv, *atth, *attl;
    cudaGetSymbolAddress((void**)&xh,   g_xh);
    cudaGetSymbolAddress((void**)&xl,   g_xl);
    cudaGetSymbolAddress((void**)&w,    g_w);
    cudaGetSymbolAddress((void**)&wo,   g_wo);
    cudaGetSymbolAddress((void**)&qkv,  g_qkv);
    cudaGetSymbolAddress((void**)&atth, g_atth);
    cudaGetSymbolAddress((void**)&attl, g_attl);

    static bool attr_done = false;
    if (!attr_done) {
        cudaFuncSetAttribute((const void*)mma_gemm<false, true, true>,
                             cudaFuncAttributeMaxDynamicSharedMemorySize,
                             GEMM_SMEM_BYTES);
        cudaFuncSetAttribute((const void*)mma_gemm<true, false, false>,
                             cudaFuncAttributeMaxDynamicSharedMemorySize,
                             GEMM_SMEM_BYTES);
        cudaFuncSetAttribute((const void*)flash_mma,
                             cudaFuncAttributeMaxDynamicSharedMemorySize,
                             FLASH_SMEM_BYTES);
        attr_done = true;
    }

    const int total4 = XF4 + 4 * WF4;
    cvt_all<<<(total4 + 255) / 256, 256>>>(x, wq, wk, wv, wo_w, xh, xl, w, wo);

    // Fused QKV projection -> single fp16 (Q pre-scaled x0.125)
    const dim3 qkv_grid(24, M_ROWS / 128);
    mma_gemm<false, true, true><<<qkv_grid, 256, GEMM_SMEM_BYTES>>>(
        xh, xl, w, nullptr, nullptr, qkv, D_MODEL, QKV_LD);

    // fp16 tensor-core causal flash attention -> attn fp16 hi/lo
    const dim3 flash_grid(S_LEN / 128, NHEAD, B_SZ);
    flash_mma<<<flash_grid, 256, FLASH_SMEM_BYTES>>>(qkv, atth, attl);

    // Output projection (fp16x2, f32 out, bias)
    const dim3 o_grid(8, M_ROWS / 128);
    mma_gemm<true, false, false><<<o_grid, 256, GEMM_SMEM_BYTES>>>(
        atth, attl, wo, wo_b, out, nullptr, D_MODEL, D_MODEL);
}

// round 16
// speedup vs baseline: 1.9049x; 1.1799x over previous
#include <cuda_runtime.h>
#include <cuda_fp16.h>
#include <cstdint>

#define B_SZ    2
#define S_LEN   2048
#define D_MODEL 1024
#define NHEAD   16
#define HD      64
#define M_ROWS  (B_SZ * S_LEN)      // 4096
#define QKV_LD  (3 * D_MODEL)       // 3072
#define DSQ     (D_MODEL * D_MODEL) // 1048576

// scratch (device globals)
__device__ __half g_xh [(size_t)M_ROWS * D_MODEL];
__device__ __half g_xl [(size_t)M_ROWS * D_MODEL];
__device__ __half g_w  [(size_t)3 * DSQ];                 // wq|wk|wv (single fp16)
__device__ __half g_wo [(size_t)DSQ];                     // wo (single fp16)
__device__ __half g_qkv[(size_t)M_ROWS * QKV_LD];         // Q(x0.125)|K|V (single fp16)
__device__ __half g_att[(size_t)M_ROWS * D_MODEL];        // attn (single fp16)

__device__ __forceinline__ uint32_t smem_u32(const void* p) {
    uint32_t a;
    asm("{ .reg .u64 t; cvta.to.shared.u64 t, %1; cvt.u32.u64 %0, t; }"
        : "=r"(a) : "l"(p));
    return a;
}

#define LDM4(r, addr) \
    asm volatile("ldmatrix.sync.aligned.m8n8.x4.shared.b16 {%0,%1,%2,%3}, [%4];" \
        : "=r"((r)[0]), "=r"((r)[1]), "=r"((r)[2]), "=r"((r)[3]) : "r"(addr))

#define LDM4T(r, addr) \
    asm volatile("ldmatrix.sync.aligned.m8n8.x4.trans.shared.b16 {%0,%1,%2,%3}, [%4];" \
        : "=r"((r)[0]), "=r"((r)[1]), "=r"((r)[2]), "=r"((r)[3]) : "r"(addr))

#define MMA_F16(d, a, b0, b1) \
    asm volatile("mma.sync.aligned.m16n8k16.row.col.f32.f16.f16.f32 " \
        "{%0,%1,%2,%3}, {%4,%5,%6,%7}, {%8,%9}, {%0,%1,%2,%3};" \
        : "+f"((d)[0]), "+f"((d)[1]), "+f"((d)[2]), "+f"((d)[3]) \
        : "r"((a)[0]), "r"((a)[1]), "r"((a)[2]), "r"((a)[3]), "r"(b0), "r"(b1))

#define CP16(dst, src) \
    asm volatile("cp.async.cg.shared.global [%0], [%1], 16;" \
        :: "r"(dst), "l"(src) : "memory")
#define CP_COMMIT() asm volatile("cp.async.commit_group;" ::: "memory")
#define CP_WAIT2()  asm volatile("cp.async.wait_group 2;" ::: "memory")

__device__ __forceinline__ uint32_t pack2h(__half a, __half b) {
    return (uint32_t)__half_as_ushort(a) |
           ((uint32_t)__half_as_ushort(b) << 16);
}

__device__ __forceinline__ uint32_t hi_lo_pack_f16(float a, float b, uint32_t& lo) {
    __half ha = __float2half_rn(a);
    __half hb = __float2half_rn(b);
    lo = pack2h(__float2half_rn(a - __half2float(ha)),
                __float2half_rn(b - __half2float(hb)));
    return pack2h(ha, hb);
}

// ---------------------------------------------------------------------------
// Fused one-shot conversions: x -> fp16 hi/lo ; weights -> single fp16
// ---------------------------------------------------------------------------
#define XF4 (M_ROWS * D_MODEL / 4)
#define WF4 (DSQ / 4)

__global__ void cvt_all(
    const float* __restrict__ x,  const float* __restrict__ wq,
    const float* __restrict__ wk, const float* __restrict__ wv,
    const float* __restrict__ wo,
    __half* __restrict__ xh, __half* __restrict__ xl,
    __half* __restrict__ w,  __half* __restrict__ wod)
{
    const int i = blockIdx.x * blockDim.x + threadIdx.x;
    if (i < XF4) {
        float4 v = reinterpret_cast<const float4*>(x)[i];
        uint32_t l0, l1;
        uint32_t h0 = hi_lo_pack_f16(v.x, v.y, l0);
        uint32_t h1 = hi_lo_pack_f16(v.z, v.w, l1);
        uint2 hh; hh.x = h0; hh.y = h1;
        uint2 ll; ll.x = l0; ll.y = l1;
        reinterpret_cast<uint2*>(xh)[i] = hh;
        reinterpret_cast<uint2*>(xl)[i] = ll;
        return;
    }
    const int k = i - XF4;
    const float* src; __half* dst; int j;
    if (k < WF4)          { src = wq; dst = w;           j = k; }
    else if (k < 2 * WF4) { src = wk; dst = w + DSQ;     j = k - WF4; }
    else if (k < 3 * WF4) { src = wv; dst = w + 2 * DSQ; j = k - 2 * WF4; }
    else if (k < 4 * WF4) { src = wo; dst = wod;         j = k - 3 * WF4; }
    else return;
    float4 v = reinterpret_cast<const float4*>(src)[j];
    uint2 hh;
    hh.x = pack2h(__float2half_rn(v.x), __float2half_rn(v.y));
    hh.y = pack2h(__float2half_rn(v.z), __float2half_rn(v.w));
    reinterpret_cast<uint2*>(dst)[j] = hh;
}

// ===========================================================================
// mma.sync fp16 GEMM: C = A @ W^T (+bias). W single fp16.
// A_SPLIT: A = fp16 hi/lo (2 MMAs/acc), else single fp16 (1 MMA/acc).
// OUT_F16: write single fp16 (+Q scale). CTA 128x128, BK=16, 4-stage cp.async.
// ===========================================================================
#define ROWB    48
#define T_AH    0
#define T_AL    6144
#define T_B     12288
#define STAGE_B 18432
#define GEMM_SMEM_BYTES (4 * STAGE_B)  // 73728

template <bool HAS_BIAS, bool OUT_F16, bool SCALE_Q8, bool A_SPLIT>
__global__ void __launch_bounds__(256, 2) mma_gemm(
    const __half* __restrict__ Ah, const __half* __restrict__ Al,
    const __half* __restrict__ W,
    const float* __restrict__ bias,
    float* __restrict__ C,
    __half* __restrict__ Ch,
    int K, int ldc)
{
    extern __shared__ __align__(128) char smem[];
    const uint32_t sbase = smem_u32(smem);
    const int tid  = threadIdx.x;
    const int lane = tid & 31;
    const int bx   = blockIdx.x;
    const int bm   = blockIdx.y * 128;
    const int bn   = (bx & 7) * 128;
    const int cn   = (bx >> 3) * D_MODEL + bn;
    const size_t woff = (size_t)(bx >> 3) * DSQ;

    const int wm = (tid >> 7) * 64;
    const int wn = ((tid >> 5) & 3) * 32;

    const uint32_t a_off = (uint32_t)(wm + (lane & 15)) * ROWB + (lane >> 4) * 16;
    const uint32_t b_off = (uint32_t)(wn + (lane >> 4) * 8 + (lane & 7)) * ROWB
                           + ((lane >> 3) & 1) * 16;

    const int lr = tid >> 1;
    const int lg = (tid & 1) * 8;
    const __half* pAh = Ah + (size_t)(bm + lr) * K + lg;
    const __half* pAl = A_SPLIT ? (Al + (size_t)(bm + lr) * K + lg) : nullptr;
    const __half* pW  = W + woff + (size_t)(bn + lr) * K + lg;
    const uint32_t soff = (uint32_t)lr * ROWB + (tid & 1) * 16;

    float acc[4][4][4];
#pragma unroll
    for (int i = 0; i < 4; i++)
#pragma unroll
        for (int j = 0; j < 4; j++)
#pragma unroll
            for (int r = 0; r < 4; r++) acc[i][j][r] = 0.f;

    const int nch = K / 16;

#pragma unroll
    for (int c = 0; c < 3; c++) {
        const uint32_t sb = sbase + c * STAGE_B;
        const int k0 = c * 16;
        CP16(sb + T_AH + soff, pAh + k0);
        if (A_SPLIT) CP16(sb + T_AL + soff, pAl + k0);
        CP16(sb + T_B  + soff, pW  + k0);
        CP_COMMIT();
    }

    for (int c = 0; c < nch; c++) {
        CP_WAIT2();
        __syncthreads();

        if (c + 3 < nch) {
            const uint32_t sb = sbase + ((c + 3) & 3) * STAGE_B;
            const int k0 = (c + 3) * 16;
            CP16(sb + T_AH + soff, pAh + k0);
            if (A_SPLIT) CP16(sb + T_AL + soff, pAl + k0);
            CP16(sb + T_B  + soff, pW  + k0);
        }
        CP_COMMIT();

        const uint32_t stb = sbase + (c & 3) * STAGE_B;
        uint32_t ah[4][4], al[4][4];
#pragma unroll
        for (int mf = 0; mf < 4; mf++) {
            LDM4(ah[mf], stb + T_AH + a_off + mf * (16 * ROWB));
            if (A_SPLIT) LDM4(al[mf], stb + T_AL + a_off + mf * (16 * ROWB));
        }
        uint32_t bh[2][4];
#pragma unroll
        for (int p = 0; p < 2; p++)
            LDM4(bh[p], stb + T_B + b_off + p * (16 * ROWB));

#pragma unroll
        for (int mf = 0; mf < 4; mf++) {
#pragma unroll
            for (int nf = 0; nf < 4; nf++) {
                const uint32_t b0 = bh[nf >> 1][(nf & 1) * 2];
                const uint32_t b1 = bh[nf >> 1][(nf & 1) * 2 + 1];
                MMA_F16(acc[mf][nf], ah[mf], b0, b1);
                if (A_SPLIT) MMA_F16(acc[mf][nf], al[mf], b0, b1);
            }
        }
    }

    const int g  = lane >> 2;
    const int t2 = (lane & 3) * 2;
    const float sc = (SCALE_Q8 && bx < 8) ? 0.125f : 1.0f;
#pragma unroll
    for (int mf = 0; mf < 4; mf++) {
#pragma unroll
        for (int nf = 0; nf < 4; nf++) {
            const int m = bm + wm + mf * 16 + g;
            const int n = cn + wn + nf * 8 + t2;
            float2 v0, v1;
            v0.x = acc[mf][nf][0]; v0.y = acc[mf][nf][1];
            v1.x = acc[mf][nf][2]; v1.y = acc[mf][nf][3];
            if (OUT_F16) {
                v0.x *= sc; v0.y *= sc; v1.x *= sc; v1.y *= sc;
                *reinterpret_cast<uint32_t*>(&Ch[(size_t)m * ldc + n]) =
                    pack2h(__float2half_rn(v0.x), __float2half_rn(v0.y));
                *reinterpret_cast<uint32_t*>(&Ch[(size_t)(m + 8) * ldc + n]) =
                    pack2h(__float2half_rn(v1.x), __float2half_rn(v1.y));
            } else {
                if (HAS_BIAS) {
                    const float2 bv = *reinterpret_cast<const float2*>(&bias[n]);
                    v0.x += bv.x; v0.y += bv.y;
                    v1.x += bv.x; v1.y += bv.y;
                }
                *reinterpret_cast<float2*>(&C[(size_t)m * ldc + n]) = v0;
                *reinterpret_cast<float2*>(&C[(size_t)(m + 8) * ldc + n]) = v1;
            }
        }
    }
}

// ===========================================================================
// fp16 tensor-core causal flash attention, 4-stage KV ring, 2 CTAs/SM.
// Q, K, V, P all single fp16. 64 MMAs/tile. attn out: single fp16.
// ===========================================================================
#define FROWB 144
#define KV_K  0
#define KV_V  9216
#define KV_STAGE 18432
#define SQH   0
#define FLASH_SMEM_BYTES (4 * KV_STAGE)   // 73728

__global__ void __launch_bounds__(256, 2) flash_mma(
    const __half* __restrict__ qkv,
    __half* __restrict__ att)
{
    extern __shared__ __align__(128) char smem[];
    const uint32_t sbase = smem_u32(smem);
    const int tid  = threadIdx.x;
    const int lane = tid & 31;
    const int w    = tid >> 5;
    const int qt   = (gridDim.x - 1) - blockIdx.x;
    const int h    = blockIdx.y;
    const int b    = blockIdx.z;

    const size_t head_base = (size_t)b * S_LEN * QKV_LD + (size_t)h * HD;

    // ---- Stage Q (single fp16, pre-scaled), consume to registers ----
    {
        const int r = tid >> 1;
        const int g0 = (tid & 1) * 4;
        const __half* qr = qkv + head_base + (size_t)(qt * 128 + r) * QKV_LD;
#pragma unroll
        for (int t = 0; t < 4; t++) {
            const int gg = g0 + t;
            *reinterpret_cast<uint4*>(smem + SQH + (uint32_t)r * FROWB + gg * 16) =
                *reinterpret_cast<const uint4*>(qr + gg * 8);
        }
    }
    __syncthreads();

    uint32_t qh[4][4];
    {
        const uint32_t a_off = (uint32_t)(w * 16 + (lane & 15)) * FROWB
                               + ((lane >> 4) * 8) * 2;
#pragma unroll
        for (int ks = 0; ks < 4; ks++)
            LDM4(qh[ks], sbase + SQH + a_off + ks * 32);
    }
    __syncthreads();

    float o[8][4];
#pragma unroll
    for (int nf = 0; nf < 8; nf++)
#pragma unroll
        for (int r = 0; r < 4; r++) o[nf][r] = 0.f;
    float m0 = -1e30f, m1 = -1e30f, l0 = 0.f, l1 = 0.f;

    const int g  = lane >> 2;
    const int t2 = (lane & 3) * 2;
    const int wrow = qt * 128 + w * 16;
    const int row0 = wrow + g;
    const int row1 = row0 + 8;

    const uint32_t kb_off = (uint32_t)((lane >> 4) * 8 + (lane & 7)) * FROWB
                            + (((lane >> 3) & 1) * 8) * 2;
    const uint32_t vt_row = (uint32_t)(lane & 15) * FROWB + ((lane >> 4) * 8) * 2;

    const int klr = tid >> 2;
    const int kg0 = (tid & 3) * 2;

    const int kt_end = 2 * qt + 1;

#pragma unroll
    for (int c = 0; c < 3; c++) {
        const uint32_t sb = sbase + c * KV_STAGE;
        const size_t rowb = head_base + (size_t)(c * 64 + klr) * QKV_LD;
#pragma unroll
        for (int t = 0; t < 2; t++) {
            const int gg = kg0 + t;
            const uint32_t off = (uint32_t)klr * FROWB + gg * 16;
            CP16(sb + KV_K + off, qkv + rowb + D_MODEL + gg * 8);
            CP16(sb + KV_V + off, qkv + rowb + 2 * D_MODEL + gg * 8);
        }
        CP_COMMIT();
    }

    for (int kt = 0; kt <= kt_end; kt++) {
        CP_WAIT2();
        __syncthreads();

        if (kt + 3 <= kt_end) {
            const uint32_t sb = sbase + ((kt + 3) & 3) * KV_STAGE;
            const size_t rowb = head_base + (size_t)((kt + 3) * 64 + klr) * QKV_LD;
#pragma unroll
            for (int t = 0; t < 2; t++) {
                const int gg = kg0 + t;
                const uint32_t off = (uint32_t)klr * FROWB + gg * 16;
                CP16(sb + KV_K + off, qkv + rowb + D_MODEL + gg * 8);
                CP16(sb + KV_V + off, qkv + rowb + 2 * D_MODEL + gg * 8);
            }
        }
        CP_COMMIT();

        const bool active = (kt * 64 <= wrow + 15);
        if (active) {
            const uint32_t stb = sbase + (kt & 3) * KV_STAGE;
            float s[8][4];
#pragma unroll
            for (int nf = 0; nf < 8; nf++)
#pragma unroll
                for (int r = 0; r < 4; r++) s[nf][r] = 0.f;

#pragma unroll
            for (int ks = 0; ks < 4; ks++) {
#pragma unroll
                for (int p = 0; p < 4; p++) {
                    uint32_t kh[4];
                    LDM4(kh, stb + KV_K + kb_off + p * (16 * FROWB) + ks * 32);
                    MMA_F16(s[2 * p],     qh[ks], kh[0], kh[1]);
                    MMA_F16(s[2 * p + 1], qh[ks], kh[2], kh[3]);
                }
            }

            if (kt * 64 + 63 > wrow) {
#pragma unroll
                for (int nf = 0; nf < 8; nf++) {
                    const int c0 = kt * 64 + nf * 8 + t2;
                    if (c0     > row0) s[nf][0] = -1e30f;
                    if (c0 + 1 > row0) s[nf][1] = -1e30f;
                    if (c0     > row1) s[nf][2] = -1e30f;
                    if (c0 + 1 > row1) s[nf][3] = -1e30f;
                }
            }

            float mx0 = s[0][0], mx1 = s[0][2];
#pragma unroll
            for (int nf = 0; nf < 8; nf++) {
                mx0 = fmaxf(mx0, fmaxf(s[nf][0], s[nf][1]));
                mx1 = fmaxf(mx1, fmaxf(s[nf][2], s[nf][3]));
            }
            mx0 = fmaxf(mx0, __shfl_xor_sync(0xffffffffu, mx0, 1));
            mx0 = fmaxf(mx0, __shfl_xor_sync(0xffffffffu, mx0, 2));
            mx1 = fmaxf(mx1, __shfl_xor_sync(0xffffffffu, mx1, 1));
            mx1 = fmaxf(mx1, __shfl_xor_sync(0xffffffffu, mx1, 2));

            const float nm0 = fmaxf(m0, mx0), nm1 = fmaxf(m1, mx1);
            const float a0 = __expf(m0 - nm0), a1 = __expf(m1 - nm1);
            m0 = nm0; m1 = nm1;

            float sum0 = 0.f, sum1 = 0.f;
#pragma unroll
            for (int nf = 0; nf < 8; nf++) {
                s[nf][0] = __expf(s[nf][0] - nm0);
                s[nf][1] = __expf(s[nf][1] - nm0);
                s[nf][2] = __expf(s[nf][2] - nm1);
                s[nf][3] = __expf(s[nf][3] - nm1);
                sum0 += s[nf][0] + s[nf][1];
                sum1 += s[nf][2] + s[nf][3];
            }
            sum0 += __shfl_xor_sync(0xffffffffu, sum0, 1);
            sum0 += __shfl_xor_sync(0xffffffffu, sum0, 2);
            sum1 += __shfl_xor_sync(0xffffffffu, sum1, 1);
            sum1 += __shfl_xor_sync(0xffffffffu, sum1, 2);
            l0 = l0 * a0 + sum0;
            l1 = l1 * a1 + sum1;

#pragma unroll
            for (int nf = 0; nf < 8; nf++) {
                o[nf][0] *= a0; o[nf][1] *= a0;
                o[nf][2] *= a1; o[nf][3] *= a1;
            }

            // ---- PV: P single fp16 ----
#pragma unroll
            for (int j = 0; j < 4; j++) {
                uint32_t ph[4];
                ph[0] = pack2h(__float2half_rn(s[2 * j][0]),     __float2half_rn(s[2 * j][1]));
                ph[1] = pack2h(__float2half_rn(s[2 * j][2]),     __float2half_rn(s[2 * j][3]));
                ph[2] = pack2h(__float2half_rn(s[2 * j + 1][0]), __float2half_rn(s[2 * j + 1][1]));
                ph[3] = pack2h(__float2half_rn(s[2 * j + 1][2]), __float2half_rn(s[2 * j + 1][3]));

                const uint32_t vbase = (uint32_t)(j * 16) * FROWB + vt_row;
#pragma unroll
                for (int hg = 0; hg < 4; hg++) {
                    uint32_t vh[4];
                    LDM4T(vh, stb + KV_V + vbase + hg * 32);
                    MMA_F16(o[2 * hg],     ph, vh[0], vh[1]);
                    MMA_F16(o[2 * hg + 1], ph, vh[2], vh[3]);
                }
            }
        }
    }

    // ---- Normalize and write attn as single fp16 ----
    const float inv0 = 1.f / l0, inv1 = 1.f / l1;
    const size_t ob = ((size_t)b * S_LEN + qt * 128 + w * 16) * D_MODEL
                      + (size_t)h * HD;
#pragma unroll
    for (int nf = 0; nf < 8; nf++) {
        const int c = nf * 8 + t2;
        *reinterpret_cast<uint32_t*>(&att[ob + (size_t)g * D_MODEL + c]) =
            pack2h(__float2half_rn(o[nf][0] * inv0), __float2half_rn(o[nf][1] * inv0));
        *reinterpret_cast<uint32_t*>(&att[ob + (size_t)(g + 8) * D_MODEL + c]) =
            pack2h(__float2half_rn(o[nf][2] * inv1), __float2half_rn(o[nf][3] * inv1));
    }
}

// ---------------------------------------------------------------------------
extern "C" void kernel_launch(void* const* d_in, const int* in_sizes, int n_in,
                              void* d_out, int out_size)
{
    const float* x    = (const float*)d_in[0];
    const float* wq   = (const float*)d_in[1];
    const float* wk   = (const float*)d_in[2];
    const float* wv   = (const float*)d_in[3];
    const float* wo_w = (const float*)d_in[4];
    const float* wo_b = (const float*)d_in[5];
    float* out = (float*)d_out;

    __half *xh, *xl, *w, *wo, *qkv, *att;
    cudaGetSymbolAddress((void**)&xh,  g_xh);
    cudaGetSymbolAddress((void**)&xl,  g_xl);
    cudaGetSymbolAddress((void**)&w,   g_w);
    cudaGetSymbolAddress((void**)&wo,  g_wo);
    cudaGetSymbolAddress((void**)&qkv, g_qkv);
    cudaGetSymbolAddress((void**)&att, g_att);

    static bool attr_done = false;
    if (!attr_done) {
        cudaFuncSetAttribute((const void*)mma_gemm<false, true, true, true>,
                             cudaFuncAttributeMaxDynamicSharedMemorySize,
                             GEMM_SMEM_BYTES);
        cudaFuncSetAttribute((const void*)mma_gemm<true, false, false, false>,
                             cudaFuncAttributeMaxDynamicSharedMemorySize,
                             GEMM_SMEM_BYTES);
        cudaFuncSetAttribute((const void*)flash_mma,
                             cudaFuncAttributeMaxDynamicSharedMemorySize,
                             FLASH_SMEM_BYTES);
        attr_done = true;
    }

    const int total4 = XF4 + 4 * WF4;
    cvt_all<<<(total4 + 255) / 256, 256>>>(x, wq, wk, wv, wo_w, xh, xl, w, wo);

    // Fused QKV projection (x hi/lo x W single) -> single fp16 (Q x0.125)
    const dim3 qkv_grid(24, M_ROWS / 128);
    mma_gemm<false, true, true, true><<<qkv_grid, 256, GEMM_SMEM_BYTES>>>(
        xh, xl, w, nullptr, nullptr, qkv, D_MODEL, QKV_LD);

    // fp16 flash attention -> attn single fp16
    const dim3 flash_grid(S_LEN / 128, NHEAD, B_SZ);
    flash_mma<<<flash_grid, 256, FLASH_SMEM_BYTES>>>(qkv, att);

    // Output projection (attn single x wo single, f32 out, bias)
    const dim3 o_grid(8, M_ROWS / 128);
    mma_gemm<true, false, false, false><<<o_grid, 256, GEMM_SMEM_BYTES>>>(
        att, nullptr, wo, wo_b, out, nullptr, D_MODEL, D_MODEL);
}

// round 17
// speedup vs baseline: 2.4728x; 1.2981x over previous
#include <cuda_runtime.h>
#include <cuda_fp16.h>
#include <cstdint>

#define B_SZ    2
#define S_LEN   2048
#define D_MODEL 1024
#define NHEAD   16
#define HD      64
#define M_ROWS  (B_SZ * S_LEN)      // 4096
#define QKV_LD  (3 * D_MODEL)       // 3072
#define DSQ     (D_MODEL * D_MODEL) // 1048576

// scratch (device globals) — everything single fp16
__device__ __half g_x  [(size_t)M_ROWS * D_MODEL];
__device__ __half g_w  [(size_t)3 * DSQ];                 // wq|wk|wv
__device__ __half g_wo [(size_t)DSQ];                     // wo
__device__ __half g_qkv[(size_t)M_ROWS * QKV_LD];         // Q(x0.125)|K|V
__device__ __half g_att[(size_t)M_ROWS * D_MODEL];        // attn

__device__ __forceinline__ uint32_t smem_u32(const void* p) {
    uint32_t a;
    asm("{ .reg .u64 t; cvta.to.shared.u64 t, %1; cvt.u32.u64 %0, t; }"
        : "=r"(a) : "l"(p));
    return a;
}

#define LDM4(r, addr) \
    asm volatile("ldmatrix.sync.aligned.m8n8.x4.shared.b16 {%0,%1,%2,%3}, [%4];" \
        : "=r"((r)[0]), "=r"((r)[1]), "=r"((r)[2]), "=r"((r)[3]) : "r"(addr))

#define LDM4T(r, addr) \
    asm volatile("ldmatrix.sync.aligned.m8n8.x4.trans.shared.b16 {%0,%1,%2,%3}, [%4];" \
        : "=r"((r)[0]), "=r"((r)[1]), "=r"((r)[2]), "=r"((r)[3]) : "r"(addr))

#define MMA_F16(d, a, b0, b1) \
    asm volatile("mma.sync.aligned.m16n8k16.row.col.f32.f16.f16.f32 " \
        "{%0,%1,%2,%3}, {%4,%5,%6,%7}, {%8,%9}, {%0,%1,%2,%3};" \
        : "+f"((d)[0]), "+f"((d)[1]), "+f"((d)[2]), "+f"((d)[3]) \
        : "r"((a)[0]), "r"((a)[1]), "r"((a)[2]), "r"((a)[3]), "r"(b0), "r"(b1))

#define CP16(dst, src) \
    asm volatile("cp.async.cg.shared.global [%0], [%1], 16;" \
        :: "r"(dst), "l"(src) : "memory")
#define CP_COMMIT() asm volatile("cp.async.commit_group;" ::: "memory")
#define CP_WAIT2()  asm volatile("cp.async.wait_group 2;" ::: "memory")

__device__ __forceinline__ uint32_t pack2h(__half a, __half b) {
    return (uint32_t)__half_as_ushort(a) |
           ((uint32_t)__half_as_ushort(b) << 16);
}

// ---------------------------------------------------------------------------
// Fused one-shot conversion: all five tensors -> single fp16
// ---------------------------------------------------------------------------
#define XF4 (M_ROWS * D_MODEL / 4)
#define WF4 (DSQ / 4)

__global__ void cvt_all(
    const float* __restrict__ x,  const float* __restrict__ wq,
    const float* __restrict__ wk, const float* __restrict__ wv,
    const float* __restrict__ wo,
    __half* __restrict__ xd, __half* __restrict__ w, __half* __restrict__ wod)
{
    const int i = blockIdx.x * blockDim.x + threadIdx.x;
    const float* src; __half* dst; int j;
    if (i < XF4)              { src = x;  dst = xd;          j = i; }
    else if (i < XF4 +   WF4) { src = wq; dst = w;           j = i - XF4; }
    else if (i < XF4 + 2*WF4) { src = wk; dst = w + DSQ;     j = i - XF4 - WF4; }
    else if (i < XF4 + 3*WF4) { src = wv; dst = w + 2 * DSQ; j = i - XF4 - 2*WF4; }
    else if (i < XF4 + 4*WF4) { src = wo; dst = wod;         j = i - XF4 - 3*WF4; }
    else return;
    float4 v = reinterpret_cast<const float4*>(src)[j];
    uint2 hh;
    hh.x = pack2h(__float2half_rn(v.x), __float2half_rn(v.y));
    hh.y = pack2h(__float2half_rn(v.z), __float2half_rn(v.w));
    reinterpret_cast<uint2*>(dst)[j] = hh;
}

// ===========================================================================
// mma.sync fp16 GEMM: C = A @ W^T (+bias). A, W single fp16 (1 MMA/acc).
// OUT_F16: write single fp16 (+Q scale). CTA 128x128, BK=16, 4-stage cp.async.
// ===========================================================================
#define ROWB    48
#define T_A     0
#define T_B     6144
#define STAGE_B 12288
#define GEMM_SMEM_BYTES (4 * STAGE_B)  // 49152

template <bool HAS_BIAS, bool OUT_F16, bool SCALE_Q8>
__global__ void __launch_bounds__(256, 2) mma_gemm(
    const __half* __restrict__ A,
    const __half* __restrict__ W,
    const float* __restrict__ bias,
    float* __restrict__ C,
    __half* __restrict__ Ch,
    int K, int ldc)
{
    extern __shared__ __align__(128) char smem[];
    const uint32_t sbase = smem_u32(smem);
    const int tid  = threadIdx.x;
    const int lane = tid & 31;
    const int bx   = blockIdx.x;
    const int bm   = blockIdx.y * 128;
    const int bn   = (bx & 7) * 128;
    const int cn   = (bx >> 3) * D_MODEL + bn;
    const size_t woff = (size_t)(bx >> 3) * DSQ;

    const int wm = (tid >> 7) * 64;
    const int wn = ((tid >> 5) & 3) * 32;

    const uint32_t a_off = (uint32_t)(wm + (lane & 15)) * ROWB + (lane >> 4) * 16;
    const uint32_t b_off = (uint32_t)(wn + (lane >> 4) * 8 + (lane & 7)) * ROWB
                           + ((lane >> 3) & 1) * 16;

    const int lr = tid >> 1;
    const int lg = (tid & 1) * 8;
    const __half* pA = A + (size_t)(bm + lr) * K + lg;
    const __half* pW = W + woff + (size_t)(bn + lr) * K + lg;
    const uint32_t soff = (uint32_t)lr * ROWB + (tid & 1) * 16;

    float acc[4][4][4];
#pragma unroll
    for (int i = 0; i < 4; i++)
#pragma unroll
        for (int j = 0; j < 4; j++)
#pragma unroll
            for (int r = 0; r < 4; r++) acc[i][j][r] = 0.f;

    const int nch = K / 16;

#pragma unroll
    for (int c = 0; c < 3; c++) {
        const uint32_t sb = sbase + c * STAGE_B;
        const int k0 = c * 16;
        CP16(sb + T_A + soff, pA + k0);
        CP16(sb + T_B + soff, pW + k0);
        CP_COMMIT();
    }

    for (int c = 0; c < nch; c++) {
        CP_WAIT2();
        __syncthreads();

        if (c + 3 < nch) {
            const uint32_t sb = sbase + ((c + 3) & 3) * STAGE_B;
            const int k0 = (c + 3) * 16;
            CP16(sb + T_A + soff, pA + k0);
            CP16(sb + T_B + soff, pW + k0);
        }
        CP_COMMIT();

        const uint32_t stb = sbase + (c & 3) * STAGE_B;
        uint32_t ah[4][4];
#pragma unroll
        for (int mf = 0; mf < 4; mf++)
            LDM4(ah[mf], stb + T_A + a_off + mf * (16 * ROWB));
        uint32_t bh[2][4];
#pragma unroll
        for (int p = 0; p < 2; p++)
            LDM4(bh[p], stb + T_B + b_off + p * (16 * ROWB));

#pragma unroll
        for (int mf = 0; mf < 4; mf++) {
#pragma unroll
            for (int nf = 0; nf < 4; nf++) {
                const uint32_t b0 = bh[nf >> 1][(nf & 1) * 2];
                const uint32_t b1 = bh[nf >> 1][(nf & 1) * 2 + 1];
                MMA_F16(acc[mf][nf], ah[mf], b0, b1);
            }
        }
    }

    const int g  = lane >> 2;
    const int t2 = (lane & 3) * 2;
    const float sc = (SCALE_Q8 && bx < 8) ? 0.125f : 1.0f;
#pragma unroll
    for (int mf = 0; mf < 4; mf++) {
#pragma unroll
        for (int nf = 0; nf < 4; nf++) {
            const int m = bm + wm + mf * 16 + g;
            const int n = cn + wn + nf * 8 + t2;
            float2 v0, v1;
            v0.x = acc[mf][nf][0]; v0.y = acc[mf][nf][1];
            v1.x = acc[mf][nf][2]; v1.y = acc[mf][nf][3];
            if (OUT_F16) {
                v0.x *= sc; v0.y *= sc; v1.x *= sc; v1.y *= sc;
                *reinterpret_cast<uint32_t*>(&Ch[(size_t)m * ldc + n]) =
                    pack2h(__float2half_rn(v0.x), __float2half_rn(v0.y));
                *reinterpret_cast<uint32_t*>(&Ch[(size_t)(m + 8) * ldc + n]) =
                    pack2h(__float2half_rn(v1.x), __float2half_rn(v1.y));
            } else {
                if (HAS_BIAS) {
                    const float2 bv = *reinterpret_cast<const float2*>(&bias[n]);
                    v0.x += bv.x; v0.y += bv.y;
                    v1.x += bv.x; v1.y += bv.y;
                }
                *reinterpret_cast<float2*>(&C[(size_t)m * ldc + n]) = v0;
                *reinterpret_cast<float2*>(&C[(size_t)(m + 8) * ldc + n]) = v1;
            }
        }
    }
}

// ===========================================================================
// fp16 tensor-core causal flash attention (R16-verified), 4-stage KV ring,
// 2 CTAs/SM. Q, K, V, P all single fp16. 64 MMAs/tile.
// ===========================================================================
#define FROWB 144
#define KV_K  0
#define KV_V  9216
#define KV_STAGE 18432
#define SQH   0
#define FLASH_SMEM_BYTES (4 * KV_STAGE)   // 73728

__global__ void __launch_bounds__(256, 2) flash_mma(
    const __half* __restrict__ qkv,
    __half* __restrict__ att)
{
    extern __shared__ __align__(128) char smem[];
    const uint32_t sbase = smem_u32(smem);
    const int tid  = threadIdx.x;
    const int lane = tid & 31;
    const int w    = tid >> 5;
    const int qt   = (gridDim.x - 1) - blockIdx.x;
    const int h    = blockIdx.y;
    const int b    = blockIdx.z;

    const size_t head_base = (size_t)b * S_LEN * QKV_LD + (size_t)h * HD;

    {
        const int r = tid >> 1;
        const int g0 = (tid & 1) * 4;
        const __half* qr = qkv + head_base + (size_t)(qt * 128 + r) * QKV_LD;
#pragma unroll
        for (int t = 0; t < 4; t++) {
            const int gg = g0 + t;
            *reinterpret_cast<uint4*>(smem + SQH + (uint32_t)r * FROWB + gg * 16) =
                *reinterpret_cast<const uint4*>(qr + gg * 8);
        }
    }
    __syncthreads();

    uint32_t qh[4][4];
    {
        const uint32_t a_off = (uint32_t)(w * 16 + (lane & 15)) * FROWB
                               + ((lane >> 4) * 8) * 2;
#pragma unroll
        for (int ks = 0; ks < 4; ks++)
            LDM4(qh[ks], sbase + SQH + a_off + ks * 32);
    }
    __syncthreads();

    float o[8][4];
#pragma unroll
    for (int nf = 0; nf < 8; nf++)
#pragma unroll
        for (int r = 0; r < 4; r++) o[nf][r] = 0.f;
    float m0 = -1e30f, m1 = -1e30f, l0 = 0.f, l1 = 0.f;

    const int g  = lane >> 2;
    const int t2 = (lane & 3) * 2;
    const int wrow = qt * 128 + w * 16;
    const int row0 = wrow + g;
    const int row1 = row0 + 8;

    const uint32_t kb_off = (uint32_t)((lane >> 4) * 8 + (lane & 7)) * FROWB
                            + (((lane >> 3) & 1) * 8) * 2;
    const uint32_t vt_row = (uint32_t)(lane & 15) * FROWB + ((lane >> 4) * 8) * 2;

    const int klr = tid >> 2;
    const int kg0 = (tid & 3) * 2;

    const int kt_end = 2 * qt + 1;

#pragma unroll
    for (int c = 0; c < 3; c++) {
        const uint32_t sb = sbase + c * KV_STAGE;
        const size_t rowb = head_base + (size_t)(c * 64 + klr) * QKV_LD;
#pragma unroll
        for (int t = 0; t < 2; t++) {
            const int gg = kg0 + t;
            const uint32_t off = (uint32_t)klr * FROWB + gg * 16;
            CP16(sb + KV_K + off, qkv + rowb + D_MODEL + gg * 8);
            CP16(sb + KV_V + off, qkv + rowb + 2 * D_MODEL + gg * 8);
        }
        CP_COMMIT();
    }

    for (int kt = 0; kt <= kt_end; kt++) {
        CP_WAIT2();
        __syncthreads();

        if (kt + 3 <= kt_end) {
            const uint32_t sb = sbase + ((kt + 3) & 3) * KV_STAGE;
            const size_t rowb = head_base + (size_t)((kt + 3) * 64 + klr) * QKV_LD;
#pragma unroll
            for (int t = 0; t < 2; t++) {
                const int gg = kg0 + t;
                const uint32_t off = (uint32_t)klr * FROWB + gg * 16;
                CP16(sb + KV_K + off, qkv + rowb + D_MODEL + gg * 8);
                CP16(sb + KV_V + off, qkv + rowb + 2 * D_MODEL + gg * 8);
            }
        }
        CP_COMMIT();

        const bool active = (kt * 64 <= wrow + 15);
        if (active) {
            const uint32_t stb = sbase + (kt & 3) * KV_STAGE;
            float s[8][4];
#pragma unroll
            for (int nf = 0; nf < 8; nf++)
#pragma unroll
                for (int r = 0; r < 4; r++) s[nf][r] = 0.f;

#pragma unroll
            for (int ks = 0; ks < 4; ks++) {
#pragma unroll
                for (int p = 0; p < 4; p++) {
                    uint32_t kh[4];
                    LDM4(kh, stb + KV_K + kb_off + p * (16 * FROWB) + ks * 32);
                    MMA_F16(s[2 * p],     qh[ks], kh[0], kh[1]);
                    MMA_F16(s[2 * p + 1], qh[ks], kh[2], kh[3]);
                }
            }

            if (kt * 64 + 63 > wrow) {
#pragma unroll
                for (int nf = 0; nf < 8; nf++) {
                    const int c0 = kt * 64 + nf * 8 + t2;
                    if (c0     > row0) s[nf][0] = -1e30f;
                    if (c0 + 1 > row0) s[nf][1] = -1e30f;
                    if (c0     > row1) s[nf][2] = -1e30f;
                    if (c0 + 1 > row1) s[nf][3] = -1e30f;
                }
            }

            float mx0 = s[0][0], mx1 = s[0][2];
#pragma unroll
            for (int nf = 0; nf < 8; nf++) {
                mx0 = fmaxf(mx0, fmaxf(s[nf][0], s[nf][1]));
                mx1 = fmaxf(mx1, fmaxf(s[nf][2], s[nf][3]));
            }
            mx0 = fmaxf(mx0, __shfl_xor_sync(0xffffffffu, mx0, 1));
            mx0 = fmaxf(mx0, __shfl_xor_sync(0xffffffffu, mx0, 2));
            mx1 = fmaxf(mx1, __shfl_xor_sync(0xffffffffu, mx1, 1));
            mx1 = fmaxf(mx1, __shfl_xor_sync(0xffffffffu, mx1, 2));

            const float nm0 = fmaxf(m0, mx0), nm1 = fmaxf(m1, mx1);
            const float a0 = __expf(m0 - nm0), a1 = __expf(m1 - nm1);
            m0 = nm0; m1 = nm1;

            float sum0 = 0.f, sum1 = 0.f;
#pragma unroll
            for (int nf = 0; nf < 8; nf++) {
                s[nf][0] = __expf(s[nf][0] - nm0);
                s[nf][1] = __expf(s[nf][1] - nm0);
                s[nf][2] = __expf(s[nf][2] - nm1);
                s[nf][3] = __expf(s[nf][3] - nm1);
                sum0 += s[nf][0] + s[nf][1];
                sum1 += s[nf][2] + s[nf][3];
            }
            sum0 += __shfl_xor_sync(0xffffffffu, sum0, 1);
            sum0 += __shfl_xor_sync(0xffffffffu, sum0, 2);
            sum1 += __shfl_xor_sync(0xffffffffu, sum1, 1);
            sum1 += __shfl_xor_sync(0xffffffffu, sum1, 2);
            l0 = l0 * a0 + sum0;
            l1 = l1 * a1 + sum1;

#pragma unroll
            for (int nf = 0; nf < 8; nf++) {
                o[nf][0] *= a0; o[nf][1] *= a0;
                o[nf][2] *= a1; o[nf][3] *= a1;
            }

#pragma unroll
            for (int j = 0; j < 4; j++) {
                uint32_t ph[4];
                ph[0] = pack2h(__float2half_rn(s[2 * j][0]),     __float2half_rn(s[2 * j][1]));
                ph[1] = pack2h(__float2half_rn(s[2 * j][2]),     __float2half_rn(s[2 * j][3]));
                ph[2] = pack2h(__float2half_rn(s[2 * j + 1][0]), __float2half_rn(s[2 * j + 1][1]));
                ph[3] = pack2h(__float2half_rn(s[2 * j + 1][2]), __float2half_rn(s[2 * j + 1][3]));

                const uint32_t vbase = (uint32_t)(j * 16) * FROWB + vt_row;
#pragma unroll
                for (int hg = 0; hg < 4; hg++) {
                    uint32_t vh[4];
                    LDM4T(vh, stb + KV_V + vbase + hg * 32);
                    MMA_F16(o[2 * hg],     ph, vh[0], vh[1]);
                    MMA_F16(o[2 * hg + 1], ph, vh[2], vh[3]);
                }
            }
        }
    }

    const float inv0 = 1.f / l0, inv1 = 1.f / l1;
    const size_t ob = ((size_t)b * S_LEN + qt * 128 + w * 16) * D_MODEL
                      + (size_t)h * HD;
#pragma unroll
    for (int nf = 0; nf < 8; nf++) {
        const int c = nf * 8 + t2;
        *reinterpret_cast<uint32_t*>(&att[ob + (size_t)g * D_MODEL + c]) =
            pack2h(__float2half_rn(o[nf][0] * inv0), __float2half_rn(o[nf][1] * inv0));
        *reinterpret_cast<uint32_t*>(&att[ob + (size_t)(g + 8) * D_MODEL + c]) =
            pack2h(__float2half_rn(o[nf][2] * inv1), __float2half_rn(o[nf][3] * inv1));
    }
}

// ---------------------------------------------------------------------------
extern "C" void kernel_launch(void* const* d_in, const int* in_sizes, int n_in,
                              void* d_out, int out_size)
{
    const float* x    = (const float*)d_in[0];
    const float* wq   = (const float*)d_in[1];
    const float* wk   = (const float*)d_in[2];
    const float* wv   = (const float*)d_in[3];
    const float* wo_w = (const float*)d_in[4];
    const float* wo_b = (const float*)d_in[5];
    float* out = (float*)d_out;

    __half *xd, *w, *wo, *qkv, *att;
    cudaGetSymbolAddress((void**)&xd,  g_x);
    cudaGetSymbolAddress((void**)&w,   g_w);
    cudaGetSymbolAddress((void**)&wo,  g_wo);
    cudaGetSymbolAddress((void**)&qkv, g_qkv);
    cudaGetSymbolAddress((void**)&att, g_att);

    static bool attr_done = false;
    if (!attr_done) {
        cudaFuncSetAttribute((const void*)mma_gemm<false, true, true>,
                             cudaFuncAttributeMaxDynamicSharedMemorySize,
                             GEMM_SMEM_BYTES);
        cudaFuncSetAttribute((const void*)mma_gemm<true, false, false>,
                             cudaFuncAttributeMaxDynamicSharedMemorySize,
                             GEMM_SMEM_BYTES);
        cudaFuncSetAttribute((const void*)flash_mma,
                             cudaFuncAttributeMaxDynamicSharedMemorySize,
                             FLASH_SMEM_BYTES);
        attr_done = true;
    }

    const int total4 = XF4 + 4 * WF4;
    cvt_all<<<(total4 + 255) / 256, 256>>>(x, wq, wk, wv, wo_w, xd, w, wo);

    // Fused QKV projection (single fp16) -> single fp16 (Q x0.125)
    const dim3 qkv_grid(24, M_ROWS / 128);
    mma_gemm<false, true, true><<<qkv_grid, 256, GEMM_SMEM_BYTES>>>(
        xd, w, nullptr, nullptr, qkv, D_MODEL, QKV_LD);

    // fp16 flash attention -> attn single fp16
    const dim3 flash_grid(S_LEN / 128, NHEAD, B_SZ);
    flash_mma<<<flash_grid, 256, FLASH_SMEM_BYTES>>>(qkv, att);

    // Output projection (single fp16, f32 out, bias)
    const dim3 o_grid(8, M_ROWS / 128);
    mma_gemm<true, false, false><<<o_grid, 256, GEMM_SMEM_BYTES>>>(
        att, wo, wo_b, out, nullptr, D_MODEL, D_MODEL);
}